// round 11
// baseline (speedup 1.0000x reference)
#include <cuda_runtime.h>
#include <cuda_bf16.h>
#include <mma.h>
#include <math.h>

using namespace nvcuda;
typedef __nv_bfloat16 bf16;

#define BB   8
#define LXT  512
#define SEQ  896
#define DIM  1024
#define NH   16
#define FFD  4096
#define NLAY 4
#define MTOK (BB*SEQ)          // 7168
#define HAM  144
#define QKVD (3*DIM)           // 3072

// ---------------- static device scratch (no allocations allowed) -------------
__device__ float g_tgt   [(size_t)MTOK*DIM];
__device__ bf16  g_tgtH  [(size_t)MTOK*DIM];
__device__ float g_x1    [(size_t)MTOK*DIM];
__device__ bf16  g_qkv   [(size_t)MTOK*QKVD];
__device__ bf16  g_vt    [(size_t)MTOK*DIM];
__device__ float g_scores[(size_t)BB*NH*SEQ*SEQ];   // 411 MB
__device__ bf16  g_probs [(size_t)BB*NH*SEQ*SEQ];   // 205 MB
__device__ bf16  g_obuf  [(size_t)MTOK*DIM];
__device__ bf16  g_hbuf  [(size_t)MTOK*FFD];
__device__ bf16  g_WqkvH [(size_t)NLAY*QKVD*DIM];
__device__ bf16  g_WoH   [(size_t)NLAY*DIM*DIM];
__device__ bf16  g_W1H   [(size_t)NLAY*FFD*DIM];
__device__ bf16  g_W2H   [(size_t)NLAY*DIM*FFD];
__device__ int   g_xmask [BB*LXT];
__device__ float g_hat   [BB*HAM];

// ------------------------------- helpers ------------------------------------
__device__ __forceinline__ float gelu_f(float x) {
    return 0.5f * x * (1.f + erff(x * 0.7071067811865476f));
}

__global__ void f2h_kernel(const float* __restrict__ s, bf16* __restrict__ d, int n) {
    for (int i = blockIdx.x * blockDim.x + threadIdx.x; i < n; i += gridDim.x * blockDim.x)
        d[i] = __float2bfloat16(s[i]);
}

// -------------------- embeddings -------------------------------------------
// x: (8,512,64). rms -> clip -> feats 1..63 @ W_nail^T + b_nail + PE(t)
__global__ void embed_x_kernel(const float* __restrict__ x,
                               const float* __restrict__ Wn,
                               const float* __restrict__ bn) {
    const float RSQ = 0.9999500037496876f;           // 1/sqrt(1.0001)
    const float PEC = -6.9077552789821368f / 1024.f; // -ln(1000)/D
    int tok0 = blockIdx.x * 8;
    int tid  = threadIdx.x;
    __shared__ float r[8][64];
    __shared__ float tS[8];
#pragma unroll
    for (int t = 0; t < 2; t++) {
        int idx = tid + t * 256;
        int tk = idx >> 6, f = idx & 63;
        float v = x[(size_t)(tok0 + tk) * 64 + f];
        int nn = isnan(v);
        if (nn) v = 0.f;
        if (f == 0) { tS[tk] = v; g_xmask[tok0 + tk] = nn; }
        float c = v * RSQ;
        r[tk][f] = fminf(fmaxf(c, -5.f), 5.f);
    }
    __syncthreads();
    float acc[4][8];
#pragma unroll
    for (int c = 0; c < 4; c++)
#pragma unroll
        for (int tk = 0; tk < 8; tk++) acc[c][tk] = 0.f;
    for (int k = 0; k < 63; k++) {
        float rv[8];
#pragma unroll
        for (int tk = 0; tk < 8; tk++) rv[tk] = r[tk][k + 1];
#pragma unroll
        for (int c = 0; c < 4; c++) {
            int n = tid + c * 256;
            float wv = Wn[(size_t)n * 63 + k];
#pragma unroll
            for (int tk = 0; tk < 8; tk++) acc[c][tk] += rv[tk] * wv;
        }
    }
#pragma unroll
    for (int c = 0; c < 4; c++) {
        int n = tid + c * 256;
        float bnv = bn[n];
        float div = expf((float)(n >> 1) * PEC);
#pragma unroll
        for (int tk = 0; tk < 8; tk++) {
            int tok = tok0 + tk;
            int b = tok >> 9, s = tok & 511;
            float ang = tS[tk] * div;
            float pe = (n & 1) ? cosf(ang) : sinf(ang);
            float v = acc[c][tk] + bnv + pe;
            size_t o = ((size_t)(b * SEQ + s)) * DIM + n;
            g_tgt[o]  = v;
            g_tgtH[o] = __float2bfloat16(v);
        }
    }
}

// w: (8,16,24,6) -> (8,384,6) rms @ W_cond^T + b_cond + PE(pos=512+rr)
__global__ void embed_w_kernel(const float* __restrict__ w,
                               const float* __restrict__ Wc,
                               const float* __restrict__ bc) {
    const float RSQ = 0.9999500037496876f;
    const float PEC = -6.9077552789821368f / 1024.f;
    int g0  = blockIdx.x * 8;   // gidx = b*384 + rr
    int tid = threadIdx.x;
    __shared__ float r[8][6];
    if (tid < 48) {
        int tk = tid / 6, k = tid - tk * 6;
        float v = w[(size_t)(g0 + tk) * 6 + k];
        if (isnan(v)) v = 0.f;
        r[tk][k] = fminf(fmaxf(v * RSQ, -5.f), 5.f);
    }
    __syncthreads();
#pragma unroll
    for (int c = 0; c < 4; c++) {
        int n = tid + c * 256;
        float bcv = bc[n];
        float wv[6];
#pragma unroll
        for (int k = 0; k < 6; k++) wv[k] = Wc[(size_t)n * 6 + k];
        float div = expf((float)(n >> 1) * PEC);
#pragma unroll
        for (int tk = 0; tk < 8; tk++) {
            int g = g0 + tk;
            int b = g / 384, rr = g - b * 384;
            float a = bcv;
#pragma unroll
            for (int k = 0; k < 6; k++) a += r[tk][k] * wv[k];
            float ang = (float)(512 + rr) * div;
            a += (n & 1) ? cosf(ang) : sinf(ang);
            size_t o = ((size_t)(b * SEQ + 512 + rr)) * DIM + n;
            g_tgt[o]  = a;
            g_tgtH[o] = __float2bfloat16(a);
        }
    }
}

// ------------------- generic batched bf16 GEMM (C = A @ B^T) -----------------
// EPI: 0 f32=acc*scale | 1 bf16=acc | 2 bf16=acc+bias | 3 f32=acc+bias+resid
//      4 bf16=gelu(acc+bias)
template<int EPI>
__global__ void __launch_bounds__(256, 2) gemm_tc(
    const bf16* __restrict__ A, const bf16* __restrict__ B,
    float* __restrict__ Cf, bf16* __restrict__ Ch,
    const float* __restrict__ bias, const float* __restrict__ resid,
    int M, int N, int K, int lda, int ldb, int ldc,
    long long sAo, long long sAi, long long sBo, long long sBi,
    long long sCo, long long sCi, int bdiv, float scale) {
    __shared__ __align__(16) bf16 As[128][40];
    __shared__ __align__(16) bf16 Bs[128][40];
    __shared__ __align__(16) float Cs[8][256];

    int z  = blockIdx.z;
    int zo = z / bdiv, zi = z - zo * bdiv;
    A += zo * sAo + zi * sAi;
    B += zo * sBo + zi * sBi;
    long long coff = zo * sCo + zi * sCi;

    int tid  = threadIdx.x;
    int warp = tid >> 5, lane = tid & 31;
    int wm = warp >> 2, wn = warp & 3;          // 2 x 4 warp grid
    int m0 = blockIdx.y * 128, n0 = blockIdx.x * 128;

    wmma::fragment<wmma::accumulator, 16, 16, 16, float> cfr[4][2];
#pragma unroll
    for (int i = 0; i < 4; i++)
#pragma unroll
        for (int j = 0; j < 2; j++) wmma::fill_fragment(cfr[i][j], 0.f);

    for (int k0 = 0; k0 < K; k0 += 32) {
        __syncthreads();
#pragma unroll
        for (int t = 0; t < 2; t++) {
            int idx = tid + t * 256;        // 0..511
            int row = idx >> 2, kc = idx & 3;
            int4 va = {0, 0, 0, 0};
            int ar = m0 + row;
            if (ar < M) va = *(const int4*)(A + (long long)ar * lda + k0 + kc * 8);
            *(int4*)(&As[row][kc * 8]) = va;
            int4 vb = {0, 0, 0, 0};
            int br = n0 + row;
            if (br < N) vb = *(const int4*)(B + (long long)br * ldb + k0 + kc * 8);
            *(int4*)(&Bs[row][kc * 8]) = vb;
        }
        __syncthreads();
#pragma unroll
        for (int ks = 0; ks < 32; ks += 16) {
            wmma::fragment<wmma::matrix_a, 16, 16, 16, bf16, wmma::row_major> af[4];
            wmma::fragment<wmma::matrix_b, 16, 16, 16, bf16, wmma::col_major> bfg[2];
#pragma unroll
            for (int i = 0; i < 4; i++)
                wmma::load_matrix_sync(af[i], &As[wm * 64 + i * 16][ks], 40);
#pragma unroll
            for (int j = 0; j < 2; j++)
                wmma::load_matrix_sync(bfg[j], &Bs[wn * 32 + j * 16][ks], 40);
#pragma unroll
            for (int i = 0; i < 4; i++)
#pragma unroll
                for (int j = 0; j < 2; j++)
                    wmma::mma_sync(cfr[i][j], af[i], bfg[j], cfr[i][j]);
        }
    }
    __syncthreads();
    float* sc = Cs[warp];
#pragma unroll
    for (int i = 0; i < 4; i++) {
#pragma unroll
        for (int j = 0; j < 2; j++) {
            wmma::store_matrix_sync(sc, cfr[i][j], 16, wmma::mem_row_major);
            __syncwarp();
            int r0 = m0 + wm * 64 + i * 16;
            int c0 = n0 + wn * 32 + j * 16;
#pragma unroll
            for (int e = 0; e < 8; e++) {
                int el = e * 32 + lane;
                int rr = el >> 4, cc = el & 15;
                int gr = r0 + rr, gc = c0 + cc;
                if (gr < M && gc < N) {
                    float v = sc[el];
                    long long o = coff + (long long)gr * ldc + gc;
                    if (EPI == 0)      Cf[o] = v * scale;
                    else if (EPI == 1) Ch[o] = __float2bfloat16(v);
                    else if (EPI == 2) Ch[o] = __float2bfloat16(v + bias[gc]);
                    else if (EPI == 3) Cf[o] = v + bias[gc] + resid[o];
                    else if (EPI == 4) Ch[o] = __float2bfloat16(gelu_f(v + bias[gc]));
                }
            }
            __syncwarp();
        }
    }
}

// ------------------- V transpose: (b,s,h,d) -> (b,h,d,s) ---------------------
__global__ void transpose_v_kernel() {
    size_t idx = (size_t)blockIdx.x * 256 + threadIdx.x;
    if (idx >= (size_t)MTOK * DIM) return;
    int s = (int)(idx % SEQ);
    size_t r = idx / SEQ;
    int d = (int)(r % 64);
    int z = (int)(r / 64);
    int b = z >> 4, h = z & 15;
    g_vt[idx] = g_qkv[(size_t)(b * SEQ + s) * QKVD + 2 * DIM + h * 64 + d];
}

// ------------------- masked softmax, fp32 -> bf16 probs ----------------------
__global__ void softmax_kernel() {
    int i = blockIdx.x;           // query row
    int z = blockIdx.y;           // b*16+h
    int b = z >> 4;
    size_t base = ((size_t)z * SEQ + i) * SEQ;
    const float* srow = g_scores + base;
    bf16* prow = g_probs + base;
    int tid = threadIdx.x, lane = tid & 31, warp = tid >> 5;

    float e[4];
    int vis[4];
    float mx = -1e30f;
#pragma unroll
    for (int t = 0; t < 4; t++) {
        int j = tid + t * 256;
        int v = 0;
        float s = -1e30f;
        if (j < SEQ) {
            v = (j < LXT) ? (g_xmask[b * LXT + j] == 0) : (j <= i);
            if (v) s = srow[j];
        }
        vis[t] = v; e[t] = s;
        mx = fmaxf(mx, s);
    }
    __shared__ float redA[8], redB[8];
#pragma unroll
    for (int o = 16; o; o >>= 1) mx = fmaxf(mx, __shfl_xor_sync(0xffffffffu, mx, o));
    if (lane == 0) redA[warp] = mx;
    __syncthreads();
    {
        float v = redA[0];
#pragma unroll
        for (int k = 1; k < 8; k++) v = fmaxf(v, redA[k]);
        mx = v;
    }
    float sum = 0.f;
#pragma unroll
    for (int t = 0; t < 4; t++) {
        if (vis[t]) { e[t] = expf(e[t] - mx); sum += e[t]; }
        else e[t] = 0.f;
    }
#pragma unroll
    for (int o = 16; o; o >>= 1) sum += __shfl_xor_sync(0xffffffffu, sum, o);
    if (lane == 0) redB[warp] = sum;
    __syncthreads();
    {
        float v = 0.f;
#pragma unroll
        for (int k = 0; k < 8; k++) v += redB[k];
        sum = v;
    }
    float inv = 1.f / sum;
#pragma unroll
    for (int t = 0; t < 4; t++) {
        int j = tid + t * 256;
        if (j < SEQ) prow[j] = __float2bfloat16(e[t] * inv);
    }
}

// --------------------------- LayerNorm --------------------------------------
__global__ void ln_kernel(const float* __restrict__ X, const float* __restrict__ g,
                          const float* __restrict__ bsh) {
    int row = blockIdx.x;
    int tid = threadIdx.x, lane = tid & 31, warp = tid >> 5;
    const float* xr = X + (size_t)row * DIM;
    float s = 0.f, s2 = 0.f;
#pragma unroll
    for (int t = 0; t < 4; t++) {
        float v = xr[tid + t * 256];
        s += v; s2 += v * v;
    }
    __shared__ float rs[8], rs2[8];
#pragma unroll
    for (int o = 16; o; o >>= 1) {
        s  += __shfl_xor_sync(0xffffffffu, s, o);
        s2 += __shfl_xor_sync(0xffffffffu, s2, o);
    }
    if (lane == 0) { rs[warp] = s; rs2[warp] = s2; }
    __syncthreads();
    float ts = 0.f, ts2 = 0.f;
#pragma unroll
    for (int k = 0; k < 8; k++) { ts += rs[k]; ts2 += rs2[k]; }
    float mean = ts * (1.f / DIM);
    float var  = ts2 * (1.f / DIM) - mean * mean;
    float inv  = rsqrtf(var + 1e-5f);
#pragma unroll
    for (int t = 0; t < 4; t++) {
        int i = tid + t * 256;
        float v = (xr[i] - mean) * inv * g[i] + bsh[i];
        size_t o = (size_t)row * DIM + i;
        g_tgt[o]  = v;
        g_tgtH[o] = __float2bfloat16(v);
    }
}

// --------------------------- output head + loss -----------------------------
__global__ void head_kernel(const float* __restrict__ Wh, const float* __restrict__ bh) {
    int n = blockIdx.x, b = blockIdx.y;
    int tid = threadIdx.x;
    const float* xr = g_tgt + (size_t)(b * SEQ + SEQ - 1) * DIM;
    const float* wr = Wh + (size_t)n * DIM;
    float s = 0.f;
    for (int d = tid; d < DIM; d += 128) s += xr[d] * wr[d];
#pragma unroll
    for (int o = 16; o; o >>= 1) s += __shfl_xor_sync(0xffffffffu, s, o);
    __shared__ float red[4];
    if ((tid & 31) == 0) red[tid >> 5] = s;
    __syncthreads();
    if (tid == 0)
        g_hat[b * HAM + n] = red[0] + red[1] + red[2] + red[3] + bh[n];
}

__global__ void loss_kernel(const float* __restrict__ y, const float* __restrict__ w,
                            float* __restrict__ out) {
    int tid = threadIdx.x, lane = tid & 31, warp = tid >> 5;
    float s = 0.f;
    for (int idx = tid; idx < BB * HAM; idx += 256) {
        int b = idx / HAM, j = idx - b * HAM;
        float resid = y[idx] - w[(size_t)(b * 16 + 15) * HAM + j];
        float d = g_hat[idx] - resid;
        s += d * d;
    }
#pragma unroll
    for (int o = 16; o; o >>= 1) s += __shfl_xor_sync(0xffffffffu, s, o);
    __shared__ float red[8];
    if (lane == 0) red[warp] = s;
    __syncthreads();
    if (tid == 0) {
        float t = 0.f;
#pragma unroll
        for (int k = 0; k < 8; k++) t += red[k];
        out[0] = t * (1.f / (BB * HAM));
    }
}

// ------------------------------- launch -------------------------------------
extern "C" void kernel_launch(void* const* d_in, const int* in_sizes, int n_in,
                              void* d_out, int out_size) {
    const float* x      = (const float*)d_in[0];
    const float* w      = (const float*)d_in[1];
    const float* y      = (const float*)d_in[2];
    const float* W_nail = (const float*)d_in[3];
    const float* b_nail = (const float*)d_in[4];
    const float* W_cond = (const float*)d_in[5];
    const float* b_cond = (const float*)d_in[6];
    const float* Wqkv   = (const float*)d_in[7];
    const float* bqkv   = (const float*)d_in[8];
    const float* Wo     = (const float*)d_in[9];
    const float* bo     = (const float*)d_in[10];
    const float* ln1g   = (const float*)d_in[11];
    const float* ln1b   = (const float*)d_in[12];
    const float* ln2g   = (const float*)d_in[13];
    const float* ln2b   = (const float*)d_in[14];
    const float* W1     = (const float*)d_in[15];
    const float* b1     = (const float*)d_in[16];
    const float* W2     = (const float*)d_in[17];
    const float* b2     = (const float*)d_in[18];
    const float* W_ham  = (const float*)d_in[19];
    const float* b_ham  = (const float*)d_in[20];

    void* p;
    bf16 *WqkvH, *WoH, *W1H, *W2H, *tgtH, *qkv, *vt, *probs, *obuf, *hbuf;
    float *tgt, *x1, *scores;
    cudaGetSymbolAddress(&p, g_WqkvH); WqkvH = (bf16*)p;
    cudaGetSymbolAddress(&p, g_WoH);   WoH   = (bf16*)p;
    cudaGetSymbolAddress(&p, g_W1H);   W1H   = (bf16*)p;
    cudaGetSymbolAddress(&p, g_W2H);   W2H   = (bf16*)p;
    cudaGetSymbolAddress(&p, g_tgtH);  tgtH  = (bf16*)p;
    cudaGetSymbolAddress(&p, g_qkv);   qkv   = (bf16*)p;
    cudaGetSymbolAddress(&p, g_vt);    vt    = (bf16*)p;
    cudaGetSymbolAddress(&p, g_probs); probs = (bf16*)p;
    cudaGetSymbolAddress(&p, g_obuf);  obuf  = (bf16*)p;
    cudaGetSymbolAddress(&p, g_hbuf);  hbuf  = (bf16*)p;
    cudaGetSymbolAddress(&p, g_tgt);    tgt    = (float*)p;
    cudaGetSymbolAddress(&p, g_x1);     x1     = (float*)p;
    cudaGetSymbolAddress(&p, g_scores); scores = (float*)p;

    // weight conversion fp32 -> bf16 (every launch: deterministic, no caching)
    f2h_kernel<<<4096, 256>>>(Wqkv, WqkvH, NLAY * QKVD * DIM);
    f2h_kernel<<<2048, 256>>>(Wo,   WoH,   NLAY * DIM * DIM);
    f2h_kernel<<<4096, 256>>>(W1,   W1H,   NLAY * FFD * DIM);
    f2h_kernel<<<4096, 256>>>(W2,   W2H,   NLAY * DIM * FFD);

    embed_x_kernel<<<512, 256>>>(x, W_nail, b_nail);
    embed_w_kernel<<<384, 256>>>(w, W_cond, b_cond);

    for (int l = 0; l < NLAY; l++) {
        // QKV projection: (7168x1024)@(3072x1024)^T + bias -> bf16
        gemm_tc<2><<<dim3(QKVD / 128, MTOK / 128, 1), 256>>>(
            tgtH, WqkvH + (size_t)l * QKVD * DIM, nullptr, qkv,
            bqkv + l * QKVD, nullptr,
            MTOK, QKVD, DIM, DIM, DIM, QKVD,
            0, 0, 0, 0, 0, 0, 1, 1.f);

        transpose_v_kernel<<<(MTOK * DIM) / 256, 256>>>();

        // scores = (Q @ K^T) / 8, batched over 128 (b,h)
        gemm_tc<0><<<dim3(SEQ / 128, SEQ / 128, BB * NH), 256>>>(
            qkv, qkv + DIM, scores, nullptr, nullptr, nullptr,
            SEQ, SEQ, 64, QKVD, QKVD, SEQ,
            (long long)SEQ * QKVD, 64, (long long)SEQ * QKVD, 64,
            (long long)NH * SEQ * SEQ, (long long)SEQ * SEQ, NH, 0.125f);

        softmax_kernel<<<dim3(SEQ, BB * NH), 256>>>();

        // O_head = P @ V, batched; write into (b,s,h*64+d)
        gemm_tc<1><<<dim3(1, SEQ / 128, BB * NH), 256>>>(
            probs, vt, nullptr, obuf, nullptr, nullptr,
            SEQ, 64, SEQ, SEQ, SEQ, DIM,
            (long long)NH * SEQ * SEQ, (long long)SEQ * SEQ,
            (long long)NH * 64 * SEQ, (long long)64 * SEQ,
            (long long)SEQ * DIM, 64, NH, 1.f);

        // O projection + bias + residual -> fp32 X1
        gemm_tc<3><<<dim3(DIM / 128, MTOK / 128, 1), 256>>>(
            obuf, WoH + (size_t)l * DIM * DIM, x1, nullptr,
            bo + l * DIM, tgt,
            MTOK, DIM, DIM, DIM, DIM, DIM,
            0, 0, 0, 0, 0, 0, 1, 1.f);

        ln_kernel<<<MTOK, 256>>>(x1, ln1g + l * DIM, ln1b + l * DIM);

        // FF1 + bias + exact GELU -> bf16
        gemm_tc<4><<<dim3(FFD / 128, MTOK / 128, 1), 256>>>(
            tgtH, W1H + (size_t)l * FFD * DIM, nullptr, hbuf,
            b1 + l * FFD, nullptr,
            MTOK, FFD, DIM, DIM, DIM, FFD,
            0, 0, 0, 0, 0, 0, 1, 1.f);

        // FF2 + bias + residual -> fp32 X1
        gemm_tc<3><<<dim3(DIM / 128, MTOK / 128, 1), 256>>>(
            hbuf, W2H + (size_t)l * DIM * FFD, x1, nullptr,
            b2 + l * DIM, tgt,
            MTOK, DIM, FFD, FFD, FFD, DIM,
            0, 0, 0, 0, 0, 0, 1, 1.f);

        ln_kernel<<<MTOK, 256>>>(x1, ln2g + l * DIM, ln2b + l * DIM);
    }

    head_kernel<<<dim3(HAM, BB), 128>>>(W_ham, b_ham);
    loss_kernel<<<1, 256>>>(y, w, (float*)d_out);
}

// round 12
// speedup vs baseline: 1.2571x; 1.2571x over previous
#include <cuda_runtime.h>
#include <cuda_bf16.h>
#include <mma.h>
#include <math.h>

using namespace nvcuda;
typedef __nv_bfloat16 bf16;

#define BB   8
#define LXT  512
#define SEQ  896
#define DIM  1024
#define NH   16
#define FFD  4096
#define NLAY 4
#define MTOK (BB*SEQ)          // 7168
#define HAM  144
#define QKVD (3*DIM)           // 3072

// ---------------- static device scratch (no allocations allowed) -------------
__device__ float g_tgt   [(size_t)MTOK*DIM];
__device__ bf16  g_tgtH  [(size_t)MTOK*DIM];
__device__ float g_x1    [(size_t)MTOK*DIM];
__device__ bf16  g_qkv   [(size_t)MTOK*QKVD];
__device__ bf16  g_obuf  [(size_t)MTOK*DIM];
__device__ bf16  g_hbuf  [(size_t)MTOK*FFD];
__device__ bf16  g_WqkvH [(size_t)NLAY*QKVD*DIM];
__device__ bf16  g_WoH   [(size_t)NLAY*DIM*DIM];
__device__ bf16  g_W1H   [(size_t)NLAY*FFD*DIM];
__device__ bf16  g_W2H   [(size_t)NLAY*DIM*FFD];
__device__ int   g_xmask [BB*LXT];
__device__ float g_hat   [BB*HAM];

// ------------------------------- helpers ------------------------------------
__device__ __forceinline__ float gelu_f(float x) {
    return 0.5f * x * (1.f + erff(x * 0.7071067811865476f));
}

__device__ __forceinline__ void cp16(void* dst, const void* src) {
    unsigned d = (unsigned)__cvta_generic_to_shared(dst);
    asm volatile("cp.async.cg.shared.global [%0], [%1], 16;\n" :: "r"(d), "l"(src));
}
#define CP_COMMIT() asm volatile("cp.async.commit_group;\n" ::: "memory")
#define CP_WAIT3()  asm volatile("cp.async.wait_group 3;\n" ::: "memory")

// vectorized fp32 -> bf16
__global__ void f2h4_kernel(const float4* __restrict__ s, __nv_bfloat162* __restrict__ d, int n4) {
    int i = blockIdx.x * blockDim.x + threadIdx.x;
    if (i < n4) {
        float4 v = s[i];
        d[2 * i]     = __floats2bfloat162_rn(v.x, v.y);
        d[2 * i + 1] = __floats2bfloat162_rn(v.z, v.w);
    }
}

// -------------------- embeddings -------------------------------------------
__global__ void embed_x_kernel(const float* __restrict__ x,
                               const float* __restrict__ Wn,
                               const float* __restrict__ bn) {
    const float RSQ = 0.9999500037496876f;           // 1/sqrt(1.0001)
    const float PEC = -6.9077552789821368f / 1024.f; // -ln(1000)/D
    int tok0 = blockIdx.x * 8;
    int tid  = threadIdx.x;
    __shared__ float r[8][64];
    __shared__ float tS[8];
#pragma unroll
    for (int t = 0; t < 2; t++) {
        int idx = tid + t * 256;
        int tk = idx >> 6, f = idx & 63;
        float v = x[(size_t)(tok0 + tk) * 64 + f];
        int nn = isnan(v);
        if (nn) v = 0.f;
        if (f == 0) { tS[tk] = v; g_xmask[tok0 + tk] = nn; }
        float c = v * RSQ;
        r[tk][f] = fminf(fmaxf(c, -5.f), 5.f);
    }
    __syncthreads();
    float acc[4][8];
#pragma unroll
    for (int c = 0; c < 4; c++)
#pragma unroll
        for (int tk = 0; tk < 8; tk++) acc[c][tk] = 0.f;
    for (int k = 0; k < 63; k++) {
        float rv[8];
#pragma unroll
        for (int tk = 0; tk < 8; tk++) rv[tk] = r[tk][k + 1];
#pragma unroll
        for (int c = 0; c < 4; c++) {
            int n = tid + c * 256;
            float wv = Wn[(size_t)n * 63 + k];
#pragma unroll
            for (int tk = 0; tk < 8; tk++) acc[c][tk] += rv[tk] * wv;
        }
    }
#pragma unroll
    for (int c = 0; c < 4; c++) {
        int n = tid + c * 256;
        float bnv = bn[n];
        float div = expf((float)(n >> 1) * PEC);
#pragma unroll
        for (int tk = 0; tk < 8; tk++) {
            int tok = tok0 + tk;
            int b = tok >> 9, s = tok & 511;
            float ang = tS[tk] * div;
            float pe = (n & 1) ? cosf(ang) : sinf(ang);
            float v = acc[c][tk] + bnv + pe;
            size_t o = ((size_t)(b * SEQ + s)) * DIM + n;
            g_tgt[o]  = v;
            g_tgtH[o] = __float2bfloat16(v);
        }
    }
}

__global__ void embed_w_kernel(const float* __restrict__ w,
                               const float* __restrict__ Wc,
                               const float* __restrict__ bc) {
    const float RSQ = 0.9999500037496876f;
    const float PEC = -6.9077552789821368f / 1024.f;
    int g0  = blockIdx.x * 8;   // gidx = b*384 + rr
    int tid = threadIdx.x;
    __shared__ float r[8][6];
    if (tid < 48) {
        int tk = tid / 6, k = tid - tk * 6;
        float v = w[(size_t)(g0 + tk) * 6 + k];
        if (isnan(v)) v = 0.f;
        r[tk][k] = fminf(fmaxf(v * RSQ, -5.f), 5.f);
    }
    __syncthreads();
#pragma unroll
    for (int c = 0; c < 4; c++) {
        int n = tid + c * 256;
        float bcv = bc[n];
        float wv[6];
#pragma unroll
        for (int k = 0; k < 6; k++) wv[k] = Wc[(size_t)n * 6 + k];
        float div = expf((float)(n >> 1) * PEC);
#pragma unroll
        for (int tk = 0; tk < 8; tk++) {
            int g = g0 + tk;
            int b = g / 384, rr = g - b * 384;
            float a = bcv;
#pragma unroll
            for (int k = 0; k < 6; k++) a += r[tk][k] * wv[k];
            float ang = (float)(512 + rr) * div;
            a += (n & 1) ? cosf(ang) : sinf(ang);
            size_t o = ((size_t)(b * SEQ + 512 + rr)) * DIM + n;
            g_tgt[o]  = a;
            g_tgtH[o] = __float2bfloat16(a);
        }
    }
}

// --------- pipelined dense GEMM (C = A @ B^T), 128x128 tile, cp.async x4 -----
// EPI: 2 bf16=acc+bias | 3 f32=acc+bias+resid | 4 bf16=gelu(acc+bias)
// M,N multiples of 128; K multiple of 32. A: MxK ld K, B: NxK ld K, C: MxN.
#define GA_STAGE 10240                       // 128*40*2 bytes
#define GB_BASE  (4*GA_STAGE)
#define G_SMEM   (8*GA_STAGE)                // 81920

template<int EPI>
__global__ void __launch_bounds__(256, 2) gemm_tc(
    const bf16* __restrict__ A, const bf16* __restrict__ B,
    float* __restrict__ Cf, bf16* __restrict__ Ch,
    const float* __restrict__ bias, const float* __restrict__ resid,
    int M, int N, int K) {
    extern __shared__ char raw[];

    int tid  = threadIdx.x;
    int warp = tid >> 5, lane = tid & 31;
    int wm = warp >> 2, wn = warp & 3;          // 2 x 4 warp grid
    int m0 = blockIdx.y * 128, n0 = blockIdx.x * 128;

    wmma::fragment<wmma::accumulator, 16, 16, 16, float> cfr[4][2];
#pragma unroll
    for (int i = 0; i < 4; i++)
#pragma unroll
        for (int j = 0; j < 2; j++) wmma::fill_fragment(cfr[i][j], 0.f);

    // thread's fixed load slots (2 chunks A + 2 chunks B per stage)
    int c0r = (tid) >> 2,        c0k = (tid) & 3;
    int c1r = (tid + 256) >> 2,  c1k = (tid + 256) & 3;
    const bf16* Arow0 = A + (size_t)(m0 + c0r) * K + c0k * 8;
    const bf16* Arow1 = A + (size_t)(m0 + c1r) * K + c1k * 8;
    const bf16* Brow0 = B + (size_t)(n0 + c0r) * K + c0k * 8;
    const bf16* Brow1 = B + (size_t)(n0 + c1r) * K + c1k * 8;
    size_t soA0 = (size_t)c0r * 80 + c0k * 16;
    size_t soA1 = (size_t)c1r * 80 + c1k * 16;

    int KT = K >> 5;
    int fetch = 0;
#pragma unroll
    for (; fetch < 3; fetch++) {
        char* as = raw + fetch * GA_STAGE;
        char* bs = raw + GB_BASE + fetch * GA_STAGE;
        int k0 = fetch * 32;
        cp16(as + soA0, Arow0 + k0);
        cp16(as + soA1, Arow1 + k0);
        cp16(bs + soA0, Brow0 + k0);
        cp16(bs + soA1, Brow1 + k0);
        CP_COMMIT();
    }

    for (int kt = 0; kt < KT; kt++) {
        if (fetch < KT) {
            int s = fetch & 3;
            char* as = raw + s * GA_STAGE;
            char* bs = raw + GB_BASE + s * GA_STAGE;
            int k0 = fetch * 32;
            cp16(as + soA0, Arow0 + k0);
            cp16(as + soA1, Arow1 + k0);
            cp16(bs + soA0, Brow0 + k0);
            cp16(bs + soA1, Brow1 + k0);
            fetch++;
        }
        CP_COMMIT();
        CP_WAIT3();
        __syncthreads();
        bf16 (*As)[40] = (bf16(*)[40])(raw + (kt & 3) * GA_STAGE);
        bf16 (*Bs)[40] = (bf16(*)[40])(raw + GB_BASE + (kt & 3) * GA_STAGE);
#pragma unroll
        for (int ks = 0; ks < 32; ks += 16) {
            wmma::fragment<wmma::matrix_a, 16, 16, 16, bf16, wmma::row_major> af[4];
            wmma::fragment<wmma::matrix_b, 16, 16, 16, bf16, wmma::col_major> bfg[2];
#pragma unroll
            for (int i = 0; i < 4; i++)
                wmma::load_matrix_sync(af[i], &As[wm * 64 + i * 16][ks], 40);
#pragma unroll
            for (int j = 0; j < 2; j++)
                wmma::load_matrix_sync(bfg[j], &Bs[wn * 32 + j * 16][ks], 40);
#pragma unroll
            for (int i = 0; i < 4; i++)
#pragma unroll
                for (int j = 0; j < 2; j++)
                    wmma::mma_sync(cfr[i][j], af[i], bfg[j], cfr[i][j]);
        }
        __syncthreads();
    }

    // epilogue: stage through smem (reuses pipeline buffers, post-sync)
    float* sc = (float*)raw + warp * 256;
#pragma unroll
    for (int i = 0; i < 4; i++) {
#pragma unroll
        for (int j = 0; j < 2; j++) {
            wmma::store_matrix_sync(sc, cfr[i][j], 16, wmma::mem_row_major);
            __syncwarp();
            int r0 = m0 + wm * 64 + i * 16;
            int c0 = n0 + wn * 32 + j * 16;
#pragma unroll
            for (int e = 0; e < 8; e++) {
                int el = e * 32 + lane;
                int rr = el >> 4, cc = el & 15;
                int gr = r0 + rr, gc = c0 + cc;
                float v = sc[el];
                size_t o = (size_t)gr * N + gc;
                if (EPI == 2)      Ch[o] = __float2bfloat16(v + bias[gc]);
                else if (EPI == 3) Cf[o] = v + bias[gc] + resid[o];
                else if (EPI == 4) Ch[o] = __float2bfloat16(gelu_f(v + bias[gc]));
            }
            __syncwarp();
        }
    }
}

// -------------------- fused flash attention ---------------------------------
// grid (7, 128): q-tile of 128 per (b,h). Online softmax, smem-resident O.
#define QS_OFF 0
#define KS_OFF 18432
#define VS_OFF 36864
#define SS_OFF 55296
#define PS_OFF 122880
#define OS_OFF 157696
#define MR_OFF 192512
#define FA_SMEM 193536

__global__ void __launch_bounds__(256) flash_kernel(const bf16* __restrict__ qkv,
                                                    bf16* __restrict__ obuf,
                                                    const int* __restrict__ xmask) {
    extern __shared__ char raw[];
    bf16  (*Qs)[72]  = (bf16(*)[72]) (raw + QS_OFF);
    bf16  (*Ks)[72]  = (bf16(*)[72]) (raw + KS_OFF);
    bf16  (*Vs)[72]  = (bf16(*)[72]) (raw + VS_OFF);
    float (*Ss)[132] = (float(*)[132])(raw + SS_OFF);
    bf16  (*Ps)[136] = (bf16(*)[136])(raw + PS_OFF);
    float (*Os)[68]  = (float(*)[68]) (raw + OS_OFF);
    float* mrow = (float*)(raw + MR_OFF);
    float* lrow = mrow + 128;

    int z = blockIdx.y;
    int b = z >> 4, h = z & 15;
    int qi = blockIdx.x, q0 = qi * 128;
    int tid = threadIdx.x, warp = tid >> 5, lane = tid & 31;
    int wm = warp >> 2, wn = warp & 3;

    const bf16* Qg = qkv + (size_t)(b * SEQ) * QKVD + h * 64;
    const bf16* Kg = Qg + DIM;
    const bf16* Vg = Qg + 2 * DIM;

    // load Q tile (128 x 64), init O, m, l
#pragma unroll
    for (int t = 0; t < 4; t++) {
        int c = tid + t * 256;
        int row = c >> 3, kc = c & 7;
        *(int4*)&Qs[row][kc * 8] = *(const int4*)(Qg + (size_t)(q0 + row) * QKVD + kc * 8);
    }
#pragma unroll
    for (int t = 0; t < 32; t++) {
        int idx = tid + t * 256;
        Os[idx >> 6][idx & 63] = 0.f;
    }
    if (tid < 128) { mrow[tid] = -1e30f; lrow[tid] = 0.f; }
    __syncthreads();

    int ktmax = (qi > 3) ? qi : 3;
    for (int kt = 0; kt <= ktmax; kt++) {
        // load K, V tiles
#pragma unroll
        for (int t = 0; t < 4; t++) {
            int c = tid + t * 256;
            int row = c >> 3, kc = c & 7;
            size_t go = (size_t)(kt * 128 + row) * QKVD + kc * 8;
            *(int4*)&Ks[row][kc * 8] = *(const int4*)(Kg + go);
            *(int4*)&Vs[row][kc * 8] = *(const int4*)(Vg + go);
        }
        __syncthreads();

        // S = Q @ K^T  (128x128, k=64)
        {
            wmma::fragment<wmma::accumulator, 16, 16, 16, float> sf[4][2];
#pragma unroll
            for (int i = 0; i < 4; i++)
#pragma unroll
                for (int j = 0; j < 2; j++) wmma::fill_fragment(sf[i][j], 0.f);
#pragma unroll
            for (int ks = 0; ks < 4; ks++) {
                wmma::fragment<wmma::matrix_a, 16, 16, 16, bf16, wmma::row_major> af[4];
                wmma::fragment<wmma::matrix_b, 16, 16, 16, bf16, wmma::col_major> bfg[2];
#pragma unroll
                for (int i = 0; i < 4; i++)
                    wmma::load_matrix_sync(af[i], &Qs[wm * 64 + i * 16][ks * 16], 72);
#pragma unroll
                for (int j = 0; j < 2; j++)
                    wmma::load_matrix_sync(bfg[j], &Ks[wn * 32 + j * 16][ks * 16], 72);
#pragma unroll
                for (int i = 0; i < 4; i++)
#pragma unroll
                    for (int j = 0; j < 2; j++)
                        wmma::mma_sync(sf[i][j], af[i], bfg[j], sf[i][j]);
            }
#pragma unroll
            for (int i = 0; i < 4; i++)
#pragma unroll
                for (int j = 0; j < 2; j++)
                    wmma::store_matrix_sync(&Ss[wm * 64 + i * 16][wn * 32 + j * 16],
                                            sf[i][j], 132, wmma::mem_row_major);
        }
        __syncthreads();

        // online softmax on rows warp*16 .. warp*16+15
        {
            int jbase = kt * 128 + lane;
            bool xval[4];
            if (kt < 4) {
#pragma unroll
                for (int t = 0; t < 4; t++)
                    xval[t] = (xmask[b * LXT + jbase + 32 * t] == 0);
            }
#pragma unroll 1
            for (int rr = 0; rr < 16; rr++) {
                int r = warp * 16 + rr;
                int ig = q0 + r;
                float v[4]; bool val[4];
                float mx = -1e30f;
#pragma unroll
                for (int t = 0; t < 4; t++) {
                    int jg = jbase + 32 * t;
                    bool valid = (kt < 4) ? xval[t] : (jg <= ig);
                    float s = valid ? Ss[r][lane + 32 * t] * 0.125f : -1e30f;
                    val[t] = valid; v[t] = s;
                    mx = fmaxf(mx, s);
                }
#pragma unroll
                for (int o = 16; o; o >>= 1) mx = fmaxf(mx, __shfl_xor_sync(0xffffffffu, mx, o));
                float mo = mrow[r];
                float mn = fmaxf(mo, mx);
                float sum = 0.f;
#pragma unroll
                for (int t = 0; t < 4; t++) {
                    float e = val[t] ? __expf(v[t] - mn) : 0.f;
                    Ps[r][lane + 32 * t] = __float2bfloat16(e);
                    sum += e;
                }
#pragma unroll
                for (int o = 16; o; o >>= 1) sum += __shfl_xor_sync(0xffffffffu, sum, o);
                float c = __expf(mo - mn);
                Os[r][lane]      *= c;
                Os[r][lane + 32] *= c;
                if (lane == 0) { mrow[r] = mn; lrow[r] = lrow[r] * c + sum; }
            }
        }
        // (no sync needed: PV uses only this warp's rows of Ps/Os, plus Vs)

        // O += P @ V  (rows warp*16..+15, n=64, k=128)
        {
            int r0 = warp * 16;
            wmma::fragment<wmma::accumulator, 16, 16, 16, float> of[4];
#pragma unroll
            for (int n = 0; n < 4; n++)
                wmma::load_matrix_sync(of[n], &Os[r0][n * 16], 68, wmma::mem_row_major);
#pragma unroll
            for (int ks = 0; ks < 8; ks++) {
                wmma::fragment<wmma::matrix_a, 16, 16, 16, bf16, wmma::row_major> af;
                wmma::load_matrix_sync(af, &Ps[r0][ks * 16], 136);
#pragma unroll
                for (int n = 0; n < 4; n++) {
                    wmma::fragment<wmma::matrix_b, 16, 16, 16, bf16, wmma::row_major> bfg;
                    wmma::load_matrix_sync(bfg, &Vs[ks * 16][n * 16], 72);
                    wmma::mma_sync(of[n], af, bfg, of[n]);
                }
            }
#pragma unroll
            for (int n = 0; n < 4; n++)
                wmma::store_matrix_sync(&Os[r0][n * 16], of[n], 68, wmma::mem_row_major);
        }
        __syncthreads();
    }

    // write O / l -> obuf (b, s, h*64 + d) bf16
#pragma unroll
    for (int t = 0; t < 32; t++) {
        int idx = tid + t * 256;
        int r = idx >> 6, d = idx & 63;
        float v = Os[r][d] / lrow[r];
        obuf[(size_t)(b * SEQ + q0 + r) * DIM + h * 64 + d] = __float2bfloat16(v);
    }
}

// --------------------------- LayerNorm --------------------------------------
__global__ void ln_kernel(const float* __restrict__ X, const float* __restrict__ g,
                          const float* __restrict__ bsh) {
    int row = blockIdx.x;
    int tid = threadIdx.x, lane = tid & 31, warp = tid >> 5;
    const float* xr = X + (size_t)row * DIM;
    float s = 0.f, s2 = 0.f;
#pragma unroll
    for (int t = 0; t < 4; t++) {
        float v = xr[tid + t * 256];
        s += v; s2 += v * v;
    }
    __shared__ float rs[8], rs2[8];
#pragma unroll
    for (int o = 16; o; o >>= 1) {
        s  += __shfl_xor_sync(0xffffffffu, s, o);
        s2 += __shfl_xor_sync(0xffffffffu, s2, o);
    }
    if (lane == 0) { rs[warp] = s; rs2[warp] = s2; }
    __syncthreads();
    float ts = 0.f, ts2 = 0.f;
#pragma unroll
    for (int k = 0; k < 8; k++) { ts += rs[k]; ts2 += rs2[k]; }
    float mean = ts * (1.f / DIM);
    float var  = ts2 * (1.f / DIM) - mean * mean;
    float inv  = rsqrtf(var + 1e-5f);
#pragma unroll
    for (int t = 0; t < 4; t++) {
        int i = tid + t * 256;
        float v = (xr[i] - mean) * inv * g[i] + bsh[i];
        size_t o = (size_t)row * DIM + i;
        g_tgt[o]  = v;
        g_tgtH[o] = __float2bfloat16(v);
    }
}

// --------------------------- output head + loss -----------------------------
__global__ void head_kernel(const float* __restrict__ Wh, const float* __restrict__ bh) {
    int n = blockIdx.x, b = blockIdx.y;
    int tid = threadIdx.x;
    const float* xr = g_tgt + (size_t)(b * SEQ + SEQ - 1) * DIM;
    const float* wr = Wh + (size_t)n * DIM;
    float s = 0.f;
    for (int d = tid; d < DIM; d += 128) s += xr[d] * wr[d];
#pragma unroll
    for (int o = 16; o; o >>= 1) s += __shfl_xor_sync(0xffffffffu, s, o);
    __shared__ float red[4];
    if ((tid & 31) == 0) red[tid >> 5] = s;
    __syncthreads();
    if (tid == 0)
        g_hat[b * HAM + n] = red[0] + red[1] + red[2] + red[3] + bh[n];
}

__global__ void loss_kernel(const float* __restrict__ y, const float* __restrict__ w,
                            float* __restrict__ out) {
    int tid = threadIdx.x, lane = tid & 31, warp = tid >> 5;
    float s = 0.f;
    for (int idx = tid; idx < BB * HAM; idx += 256) {
        int b = idx / HAM, j = idx - b * HAM;
        float resid = y[idx] - w[(size_t)(b * 16 + 15) * HAM + j];
        float d = g_hat[idx] - resid;
        s += d * d;
    }
#pragma unroll
    for (int o = 16; o; o >>= 1) s += __shfl_xor_sync(0xffffffffu, s, o);
    __shared__ float red[8];
    if (lane == 0) red[warp] = s;
    __syncthreads();
    if (tid == 0) {
        float t = 0.f;
#pragma unroll
        for (int k = 0; k < 8; k++) t += red[k];
        out[0] = t * (1.f / (BB * HAM));
    }
}

// ------------------------------- launch -------------------------------------
extern "C" void kernel_launch(void* const* d_in, const int* in_sizes, int n_in,
                              void* d_out, int out_size) {
    const float* x      = (const float*)d_in[0];
    const float* w      = (const float*)d_in[1];
    const float* y      = (const float*)d_in[2];
    const float* W_nail = (const float*)d_in[3];
    const float* b_nail = (const float*)d_in[4];
    const float* W_cond = (const float*)d_in[5];
    const float* b_cond = (const float*)d_in[6];
    const float* Wqkv   = (const float*)d_in[7];
    const float* bqkv   = (const float*)d_in[8];
    const float* Wo     = (const float*)d_in[9];
    const float* bo     = (const float*)d_in[10];
    const float* ln1g   = (const float*)d_in[11];
    const float* ln1b   = (const float*)d_in[12];
    const float* ln2g   = (const float*)d_in[13];
    const float* ln2b   = (const float*)d_in[14];
    const float* W1     = (const float*)d_in[15];
    const float* b1     = (const float*)d_in[16];
    const float* W2     = (const float*)d_in[17];
    const float* b2     = (const float*)d_in[18];
    const float* W_ham  = (const float*)d_in[19];
    const float* b_ham  = (const float*)d_in[20];

    void* p;
    bf16 *WqkvH, *WoH, *W1H, *W2H, *tgtH, *qkv, *obuf, *hbuf;
    float *tgt, *x1;
    int* xmask;
    cudaGetSymbolAddress(&p, g_WqkvH); WqkvH = (bf16*)p;
    cudaGetSymbolAddress(&p, g_WoH);   WoH   = (bf16*)p;
    cudaGetSymbolAddress(&p, g_W1H);   W1H   = (bf16*)p;
    cudaGetSymbolAddress(&p, g_W2H);   W2H   = (bf16*)p;
    cudaGetSymbolAddress(&p, g_tgtH);  tgtH  = (bf16*)p;
    cudaGetSymbolAddress(&p, g_qkv);   qkv   = (bf16*)p;
    cudaGetSymbolAddress(&p, g_obuf);  obuf  = (bf16*)p;
    cudaGetSymbolAddress(&p, g_hbuf);  hbuf  = (bf16*)p;
    cudaGetSymbolAddress(&p, g_tgt);   tgt   = (float*)p;
    cudaGetSymbolAddress(&p, g_x1);    x1    = (float*)p;
    cudaGetSymbolAddress(&p, g_xmask); xmask = (int*)p;

    cudaFuncSetAttribute(gemm_tc<2>, cudaFuncAttributeMaxDynamicSharedMemorySize, G_SMEM);
    cudaFuncSetAttribute(gemm_tc<3>, cudaFuncAttributeMaxDynamicSharedMemorySize, G_SMEM);
    cudaFuncSetAttribute(gemm_tc<4>, cudaFuncAttributeMaxDynamicSharedMemorySize, G_SMEM);
    cudaFuncSetAttribute(flash_kernel, cudaFuncAttributeMaxDynamicSharedMemorySize, FA_SMEM);

    // weight conversion fp32 -> bf16 (every launch: deterministic)
    {
        int n;
        n = NLAY * QKVD * DIM / 4; f2h4_kernel<<<(n + 255) / 256, 256>>>((const float4*)Wqkv, (__nv_bfloat162*)WqkvH, n);
        n = NLAY * DIM * DIM / 4;  f2h4_kernel<<<(n + 255) / 256, 256>>>((const float4*)Wo,   (__nv_bfloat162*)WoH,   n);
        n = NLAY * FFD * DIM / 4;  f2h4_kernel<<<(n + 255) / 256, 256>>>((const float4*)W1,   (__nv_bfloat162*)W1H,   n);
        n = NLAY * DIM * FFD / 4;  f2h4_kernel<<<(n + 255) / 256, 256>>>((const float4*)W2,   (__nv_bfloat162*)W2H,   n);
    }

    embed_x_kernel<<<512, 256>>>(x, W_nail, b_nail);
    embed_w_kernel<<<384, 256>>>(w, W_cond, b_cond);

    for (int l = 0; l < NLAY; l++) {
        // QKV projection: (7168x1024)@(3072x1024)^T + bias -> bf16
        gemm_tc<2><<<dim3(QKVD / 128, MTOK / 128), 256, G_SMEM>>>(
            tgtH, WqkvH + (size_t)l * QKVD * DIM, nullptr, qkv,
            bqkv + l * QKVD, nullptr, MTOK, QKVD, DIM);

        // fused attention -> obuf (b, s, h*64+d) bf16
        flash_kernel<<<dim3(SEQ / 128, BB * NH), 256, FA_SMEM>>>(qkv, obuf, xmask);

        // O projection + bias + residual -> fp32 X1
        gemm_tc<3><<<dim3(DIM / 128, MTOK / 128), 256, G_SMEM>>>(
            obuf, WoH + (size_t)l * DIM * DIM, x1, nullptr,
            bo + l * DIM, tgt, MTOK, DIM, DIM);

        ln_kernel<<<MTOK, 256>>>(x1, ln1g + l * DIM, ln1b + l * DIM);

        // FF1 + bias + exact GELU -> bf16
        gemm_tc<4><<<dim3(FFD / 128, MTOK / 128), 256, G_SMEM>>>(
            tgtH, W1H + (size_t)l * FFD * DIM, nullptr, hbuf,
            b1 + l * FFD, nullptr, MTOK, FFD, DIM);

        // FF2 + bias + residual -> fp32 X1
        gemm_tc<3><<<dim3(DIM / 128, MTOK / 128), 256, G_SMEM>>>(
            hbuf, W2H + (size_t)l * DIM * FFD, x1, nullptr,
            b2 + l * DIM, tgt, MTOK, DIM, FFD);

        ln_kernel<<<MTOK, 256>>>(x1, ln2g + l * DIM, ln2b + l * DIM);
    }

    head_kernel<<<dim3(HAM, BB), 128>>>(W_ham, b_ham);
    loss_kernel<<<1, 256>>>(y, w, (float*)d_out);
}

// round 13
// speedup vs baseline: 1.2610x; 1.0031x over previous
#include <cuda_runtime.h>
#include <cuda_bf16.h>
#include <mma.h>
#include <math.h>

using namespace nvcuda;
typedef __nv_bfloat16 bf16;

#define BB   8
#define LXT  512
#define SEQ  896
#define DIM  1024
#define NH   16
#define FFD  4096
#define NLAY 4
#define MTOK (BB*SEQ)          // 7168
#define HAM  144
#define QKVD (3*DIM)           // 3072

// ---------------- static device scratch (no allocations allowed) -------------
__device__ float g_tgt   [(size_t)MTOK*DIM];
__device__ bf16  g_tgtH  [(size_t)MTOK*DIM];
__device__ float g_x1    [(size_t)MTOK*DIM];
__device__ bf16  g_qkv   [(size_t)MTOK*QKVD];
__device__ bf16  g_obuf  [(size_t)MTOK*DIM];
__device__ bf16  g_hbuf  [(size_t)MTOK*FFD];
__device__ bf16  g_WqkvH [(size_t)NLAY*QKVD*DIM];
__device__ bf16  g_WoH   [(size_t)NLAY*DIM*DIM];
__device__ bf16  g_W1H   [(size_t)NLAY*FFD*DIM];
__device__ bf16  g_W2H   [(size_t)NLAY*DIM*FFD];
__device__ int   g_xmask [BB*LXT];
__device__ float g_hat   [BB*HAM];

// ------------------------------- helpers ------------------------------------
__device__ __forceinline__ float gelu_f(float x) {
    return 0.5f * x * (1.f + erff(x * 0.7071067811865476f));
}

__device__ __forceinline__ void cp16(void* dst, const void* src) {
    unsigned d = (unsigned)__cvta_generic_to_shared(dst);
    asm volatile("cp.async.cg.shared.global [%0], [%1], 16;\n" :: "r"(d), "l"(src));
}
#define CP_COMMIT() asm volatile("cp.async.commit_group;\n" ::: "memory")
#define CP_WAIT3()  asm volatile("cp.async.wait_group 3;\n" ::: "memory")

// vectorized fp32 -> bf16
__global__ void f2h4_kernel(const float4* __restrict__ s, __nv_bfloat162* __restrict__ d, int n4) {
    int i = blockIdx.x * blockDim.x + threadIdx.x;
    if (i < n4) {
        float4 v = s[i];
        d[2 * i]     = __floats2bfloat162_rn(v.x, v.y);
        d[2 * i + 1] = __floats2bfloat162_rn(v.z, v.w);
    }
}

// -------------------- embeddings -------------------------------------------
__global__ void embed_x_kernel(const float* __restrict__ x,
                               const float* __restrict__ Wn,
                               const float* __restrict__ bn) {
    const float RSQ = 0.9999500037496876f;           // 1/sqrt(1.0001)
    const float PEC = -6.9077552789821368f / 1024.f; // -ln(1000)/D
    int tok0 = blockIdx.x * 8;
    int tid  = threadIdx.x;
    __shared__ float r[8][64];
    __shared__ float tS[8];
#pragma unroll
    for (int t = 0; t < 2; t++) {
        int idx = tid + t * 256;
        int tk = idx >> 6, f = idx & 63;
        float v = x[(size_t)(tok0 + tk) * 64 + f];
        int nn = isnan(v);
        if (nn) v = 0.f;
        if (f == 0) { tS[tk] = v; g_xmask[tok0 + tk] = nn; }
        float c = v * RSQ;
        r[tk][f] = fminf(fmaxf(c, -5.f), 5.f);
    }
    __syncthreads();
    float acc[4][8];
#pragma unroll
    for (int c = 0; c < 4; c++)
#pragma unroll
        for (int tk = 0; tk < 8; tk++) acc[c][tk] = 0.f;
    for (int k = 0; k < 63; k++) {
        float rv[8];
#pragma unroll
        for (int tk = 0; tk < 8; tk++) rv[tk] = r[tk][k + 1];
#pragma unroll
        for (int c = 0; c < 4; c++) {
            int n = tid + c * 256;
            float wv = Wn[(size_t)n * 63 + k];
#pragma unroll
            for (int tk = 0; tk < 8; tk++) acc[c][tk] += rv[tk] * wv;
        }
    }
#pragma unroll
    for (int c = 0; c < 4; c++) {
        int n = tid + c * 256;
        float bnv = bn[n];
        float div = expf((float)(n >> 1) * PEC);
#pragma unroll
        for (int tk = 0; tk < 8; tk++) {
            int tok = tok0 + tk;
            int b = tok >> 9, s = tok & 511;
            float ang = tS[tk] * div;
            float pe = (n & 1) ? cosf(ang) : sinf(ang);
            float v = acc[c][tk] + bnv + pe;
            size_t o = ((size_t)(b * SEQ + s)) * DIM + n;
            g_tgt[o]  = v;
            g_tgtH[o] = __float2bfloat16(v);
        }
    }
}

__global__ void embed_w_kernel(const float* __restrict__ w,
                               const float* __restrict__ Wc,
                               const float* __restrict__ bc) {
    const float RSQ = 0.9999500037496876f;
    const float PEC = -6.9077552789821368f / 1024.f;
    int g0  = blockIdx.x * 8;   // gidx = b*384 + rr
    int tid = threadIdx.x;
    __shared__ float r[8][6];
    if (tid < 48) {
        int tk = tid / 6, k = tid - tk * 6;
        float v = w[(size_t)(g0 + tk) * 6 + k];
        if (isnan(v)) v = 0.f;
        r[tk][k] = fminf(fmaxf(v * RSQ, -5.f), 5.f);
    }
    __syncthreads();
#pragma unroll
    for (int c = 0; c < 4; c++) {
        int n = tid + c * 256;
        float bcv = bc[n];
        float wv[6];
#pragma unroll
        for (int k = 0; k < 6; k++) wv[k] = Wc[(size_t)n * 6 + k];
        float div = expf((float)(n >> 1) * PEC);
#pragma unroll
        for (int tk = 0; tk < 8; tk++) {
            int g = g0 + tk;
            int b = g / 384, rr = g - b * 384;
            float a = bcv;
#pragma unroll
            for (int k = 0; k < 6; k++) a += r[tk][k] * wv[k];
            float ang = (float)(512 + rr) * div;
            a += (n & 1) ? cosf(ang) : sinf(ang);
            size_t o = ((size_t)(b * SEQ + 512 + rr)) * DIM + n;
            g_tgt[o]  = a;
            g_tgtH[o] = __float2bfloat16(a);
        }
    }
}

// --------- pipelined dense GEMM (C = A @ B^T), 128x128 tile, cp.async x4 -----
// EPI: 2 bf16=acc+bias | 3 f32=acc+bias+resid | 4 bf16=gelu(acc+bias)
// M,N multiples of 128; K multiple of 32. A: MxK ld K, B: NxK ld K, C: MxN.
#define GA_STAGE 10240                       // 128*40*2 bytes
#define GB_BASE  (4*GA_STAGE)
#define G_SMEM   (8*GA_STAGE)                // 81920

template<int EPI>
__global__ void __launch_bounds__(256, 2) gemm_tc(
    const bf16* __restrict__ A, const bf16* __restrict__ B,
    float* __restrict__ Cf, bf16* __restrict__ Ch,
    const float* __restrict__ bias, const float* __restrict__ resid,
    int M, int N, int K) {
    extern __shared__ char raw[];

    int tid  = threadIdx.x;
    int warp = tid >> 5, lane = tid & 31;
    int wm = warp >> 2, wn = warp & 3;          // 2 x 4 warp grid
    int m0 = blockIdx.y * 128, n0 = blockIdx.x * 128;

    wmma::fragment<wmma::accumulator, 16, 16, 16, float> cfr[4][2];
#pragma unroll
    for (int i = 0; i < 4; i++)
#pragma unroll
        for (int j = 0; j < 2; j++) wmma::fill_fragment(cfr[i][j], 0.f);

    // thread's fixed load slots (2 chunks A + 2 chunks B per stage)
    int c0r = (tid) >> 2,        c0k = (tid) & 3;
    int c1r = (tid + 256) >> 2,  c1k = (tid + 256) & 3;
    const bf16* Arow0 = A + (size_t)(m0 + c0r) * K + c0k * 8;
    const bf16* Arow1 = A + (size_t)(m0 + c1r) * K + c1k * 8;
    const bf16* Brow0 = B + (size_t)(n0 + c0r) * K + c0k * 8;
    const bf16* Brow1 = B + (size_t)(n0 + c1r) * K + c1k * 8;
    size_t soA0 = (size_t)c0r * 80 + c0k * 16;
    size_t soA1 = (size_t)c1r * 80 + c1k * 16;

    int KT = K >> 5;
    int fetch = 0;
#pragma unroll
    for (; fetch < 3; fetch++) {
        char* as = raw + fetch * GA_STAGE;
        char* bs = raw + GB_BASE + fetch * GA_STAGE;
        int k0 = fetch * 32;
        cp16(as + soA0, Arow0 + k0);
        cp16(as + soA1, Arow1 + k0);
        cp16(bs + soA0, Brow0 + k0);
        cp16(bs + soA1, Brow1 + k0);
        CP_COMMIT();
    }

    for (int kt = 0; kt < KT; kt++) {
        if (fetch < KT) {
            int s = fetch & 3;
            char* as = raw + s * GA_STAGE;
            char* bs = raw + GB_BASE + s * GA_STAGE;
            int k0 = fetch * 32;
            cp16(as + soA0, Arow0 + k0);
            cp16(as + soA1, Arow1 + k0);
            cp16(bs + soA0, Brow0 + k0);
            cp16(bs + soA1, Brow1 + k0);
            fetch++;
        }
        CP_COMMIT();
        CP_WAIT3();
        __syncthreads();
        bf16 (*As)[40] = (bf16(*)[40])(raw + (kt & 3) * GA_STAGE);
        bf16 (*Bs)[40] = (bf16(*)[40])(raw + GB_BASE + (kt & 3) * GA_STAGE);
#pragma unroll
        for (int ks = 0; ks < 32; ks += 16) {
            wmma::fragment<wmma::matrix_a, 16, 16, 16, bf16, wmma::row_major> af[4];
            wmma::fragment<wmma::matrix_b, 16, 16, 16, bf16, wmma::col_major> bfg[2];
#pragma unroll
            for (int i = 0; i < 4; i++)
                wmma::load_matrix_sync(af[i], &As[wm * 64 + i * 16][ks], 40);
#pragma unroll
            for (int j = 0; j < 2; j++)
                wmma::load_matrix_sync(bfg[j], &Bs[wn * 32 + j * 16][ks], 40);
#pragma unroll
            for (int i = 0; i < 4; i++)
#pragma unroll
                for (int j = 0; j < 2; j++)
                    wmma::mma_sync(cfr[i][j], af[i], bfg[j], cfr[i][j]);
        }
        __syncthreads();
    }

    // epilogue: stage through smem (reuses pipeline buffers, post-sync)
    float* sc = (float*)raw + warp * 256;
#pragma unroll
    for (int i = 0; i < 4; i++) {
#pragma unroll
        for (int j = 0; j < 2; j++) {
            wmma::store_matrix_sync(sc, cfr[i][j], 16, wmma::mem_row_major);
            __syncwarp();
            int r0 = m0 + wm * 64 + i * 16;
            int c0 = n0 + wn * 32 + j * 16;
#pragma unroll
            for (int e = 0; e < 8; e++) {
                int el = e * 32 + lane;
                int rr = el >> 4, cc = el & 15;
                int gr = r0 + rr, gc = c0 + cc;
                float v = sc[el];
                size_t o = (size_t)gr * N + gc;
                if (EPI == 2)      Ch[o] = __float2bfloat16(v + bias[gc]);
                else if (EPI == 3) Cf[o] = v + bias[gc] + resid[o];
                else if (EPI == 4) Ch[o] = __float2bfloat16(gelu_f(v + bias[gc]));
            }
            __syncwarp();
        }
    }
}

// -------------------- fused flash attention ---------------------------------
// grid (7, 128): q-tile of 128 per (b,h). Online softmax, smem-resident O.
#define QS_OFF 0
#define KS_OFF 18432
#define VS_OFF 36864
#define SS_OFF 55296
#define PS_OFF 122880
#define OS_OFF 157696
#define MR_OFF 192512
#define FA_SMEM 193536

__global__ void __launch_bounds__(256) flash_kernel(const bf16* __restrict__ qkv,
                                                    bf16* __restrict__ obuf,
                                                    const int* __restrict__ xmask) {
    extern __shared__ char raw[];
    bf16  (*Qs)[72]  = (bf16(*)[72]) (raw + QS_OFF);
    bf16  (*Ks)[72]  = (bf16(*)[72]) (raw + KS_OFF);
    bf16  (*Vs)[72]  = (bf16(*)[72]) (raw + VS_OFF);
    float (*Ss)[132] = (float(*)[132])(raw + SS_OFF);
    bf16  (*Ps)[136] = (bf16(*)[136])(raw + PS_OFF);
    float (*Os)[68]  = (float(*)[68]) (raw + OS_OFF);
    float* mrow = (float*)(raw + MR_OFF);
    float* lrow = mrow + 128;

    int z = blockIdx.y;
    int b = z >> 4, h = z & 15;
    int qi = blockIdx.x, q0 = qi * 128;
    int tid = threadIdx.x, warp = tid >> 5, lane = tid & 31;
    int wm = warp >> 2, wn = warp & 3;

    const bf16* Qg = qkv + (size_t)(b * SEQ) * QKVD + h * 64;
    const bf16* Kg = Qg + DIM;
    const bf16* Vg = Qg + 2 * DIM;

    // load Q tile (128 x 64), init O, m, l
#pragma unroll
    for (int t = 0; t < 4; t++) {
        int c = tid + t * 256;
        int row = c >> 3, kc = c & 7;
        *(int4*)&Qs[row][kc * 8] = *(const int4*)(Qg + (size_t)(q0 + row) * QKVD + kc * 8);
    }
#pragma unroll
    for (int t = 0; t < 32; t++) {
        int idx = tid + t * 256;
        Os[idx >> 6][idx & 63] = 0.f;
    }
    if (tid < 128) { mrow[tid] = -1e30f; lrow[tid] = 0.f; }
    __syncthreads();

    int ktmax = (qi > 3) ? qi : 3;
    for (int kt = 0; kt <= ktmax; kt++) {
        // load K, V tiles
#pragma unroll
        for (int t = 0; t < 4; t++) {
            int c = tid + t * 256;
            int row = c >> 3, kc = c & 7;
            size_t go = (size_t)(kt * 128 + row) * QKVD + kc * 8;
            *(int4*)&Ks[row][kc * 8] = *(const int4*)(Kg + go);
            *(int4*)&Vs[row][kc * 8] = *(const int4*)(Vg + go);
        }
        __syncthreads();

        // S = Q @ K^T  (128x128, k=64)
        {
            wmma::fragment<wmma::accumulator, 16, 16, 16, float> sf[4][2];
#pragma unroll
            for (int i = 0; i < 4; i++)
#pragma unroll
                for (int j = 0; j < 2; j++) wmma::fill_fragment(sf[i][j], 0.f);
#pragma unroll
            for (int ks = 0; ks < 4; ks++) {
                wmma::fragment<wmma::matrix_a, 16, 16, 16, bf16, wmma::row_major> af[4];
                wmma::fragment<wmma::matrix_b, 16, 16, 16, bf16, wmma::col_major> bfg[2];
#pragma unroll
                for (int i = 0; i < 4; i++)
                    wmma::load_matrix_sync(af[i], &Qs[wm * 64 + i * 16][ks * 16], 72);
#pragma unroll
                for (int j = 0; j < 2; j++)
                    wmma::load_matrix_sync(bfg[j], &Ks[wn * 32 + j * 16][ks * 16], 72);
#pragma unroll
                for (int i = 0; i < 4; i++)
#pragma unroll
                    for (int j = 0; j < 2; j++)
                        wmma::mma_sync(sf[i][j], af[i], bfg[j], sf[i][j]);
            }
#pragma unroll
            for (int i = 0; i < 4; i++)
#pragma unroll
                for (int j = 0; j < 2; j++)
                    wmma::store_matrix_sync(&Ss[wm * 64 + i * 16][wn * 32 + j * 16],
                                            sf[i][j], 132, wmma::mem_row_major);
        }
        __syncthreads();

        // online softmax on rows warp*16 .. warp*16+15
        {
            int jbase = kt * 128 + lane;
            bool xval[4];
            if (kt < 4) {
#pragma unroll
                for (int t = 0; t < 4; t++)
                    xval[t] = (xmask[b * LXT + jbase + 32 * t] == 0);
            }
#pragma unroll 1
            for (int rr = 0; rr < 16; rr++) {
                int r = warp * 16 + rr;
                int ig = q0 + r;
                float v[4]; bool val[4];
                float mx = -1e30f;
#pragma unroll
                for (int t = 0; t < 4; t++) {
                    int jg = jbase + 32 * t;
                    bool valid = (kt < 4) ? xval[t] : (jg <= ig);
                    float s = valid ? Ss[r][lane + 32 * t] * 0.125f : -1e30f;
                    val[t] = valid; v[t] = s;
                    mx = fmaxf(mx, s);
                }
#pragma unroll
                for (int o = 16; o; o >>= 1) mx = fmaxf(mx, __shfl_xor_sync(0xffffffffu, mx, o));
                float mo = mrow[r];
                float mn = fmaxf(mo, mx);
                float sum = 0.f;
#pragma unroll
                for (int t = 0; t < 4; t++) {
                    float e = val[t] ? __expf(v[t] - mn) : 0.f;
                    Ps[r][lane + 32 * t] = __float2bfloat16(e);
                    sum += e;
                }
#pragma unroll
                for (int o = 16; o; o >>= 1) sum += __shfl_xor_sync(0xffffffffu, sum, o);
                float c = __expf(mo - mn);
                Os[r][lane]      *= c;
                Os[r][lane + 32] *= c;
                if (lane == 0) { mrow[r] = mn; lrow[r] = lrow[r] * c + sum; }
            }
        }
        // (no sync needed: PV uses only this warp's rows of Ps/Os, plus Vs)

        // O += P @ V  (rows warp*16..+15, n=64, k=128)
        {
            int r0 = warp * 16;
            wmma::fragment<wmma::accumulator, 16, 16, 16, float> of[4];
#pragma unroll
            for (int n = 0; n < 4; n++)
                wmma::load_matrix_sync(of[n], &Os[r0][n * 16], 68, wmma::mem_row_major);
#pragma unroll
            for (int ks = 0; ks < 8; ks++) {
                wmma::fragment<wmma::matrix_a, 16, 16, 16, bf16, wmma::row_major> af;
                wmma::load_matrix_sync(af, &Ps[r0][ks * 16], 136);
#pragma unroll
                for (int n = 0; n < 4; n++) {
                    wmma::fragment<wmma::matrix_b, 16, 16, 16, bf16, wmma::row_major> bfg;
                    wmma::load_matrix_sync(bfg, &Vs[ks * 16][n * 16], 72);
                    wmma::mma_sync(of[n], af, bfg, of[n]);
                }
            }
#pragma unroll
            for (int n = 0; n < 4; n++)
                wmma::store_matrix_sync(&Os[r0][n * 16], of[n], 68, wmma::mem_row_major);
        }
        __syncthreads();
    }

    // write O / l -> obuf (b, s, h*64 + d) bf16
#pragma unroll
    for (int t = 0; t < 32; t++) {
        int idx = tid + t * 256;
        int r = idx >> 6, d = idx & 63;
        float v = Os[r][d] / lrow[r];
        obuf[(size_t)(b * SEQ + q0 + r) * DIM + h * 64 + d] = __float2bfloat16(v);
    }
}

// --------------------------- LayerNorm --------------------------------------
__global__ void ln_kernel(const float* __restrict__ X, const float* __restrict__ g,
                          const float* __restrict__ bsh) {
    int row = blockIdx.x;
    int tid = threadIdx.x, lane = tid & 31, warp = tid >> 5;
    const float* xr = X + (size_t)row * DIM;
    float s = 0.f, s2 = 0.f;
#pragma unroll
    for (int t = 0; t < 4; t++) {
        float v = xr[tid + t * 256];
        s += v; s2 += v * v;
    }
    __shared__ float rs[8], rs2[8];
#pragma unroll
    for (int o = 16; o; o >>= 1) {
        s  += __shfl_xor_sync(0xffffffffu, s, o);
        s2 += __shfl_xor_sync(0xffffffffu, s2, o);
    }
    if (lane == 0) { rs[warp] = s; rs2[warp] = s2; }
    __syncthreads();
    float ts = 0.f, ts2 = 0.f;
#pragma unroll
    for (int k = 0; k < 8; k++) { ts += rs[k]; ts2 += rs2[k]; }
    float mean = ts * (1.f / DIM);
    float var  = ts2 * (1.f / DIM) - mean * mean;
    float inv  = rsqrtf(var + 1e-5f);
#pragma unroll
    for (int t = 0; t < 4; t++) {
        int i = tid + t * 256;
        float v = (xr[i] - mean) * inv * g[i] + bsh[i];
        size_t o = (size_t)row * DIM + i;
        g_tgt[o]  = v;
        g_tgtH[o] = __float2bfloat16(v);
    }
}

// --------------------------- output head + loss -----------------------------
__global__ void head_kernel(const float* __restrict__ Wh, const float* __restrict__ bh) {
    int n = blockIdx.x, b = blockIdx.y;
    int tid = threadIdx.x;
    const float* xr = g_tgt + (size_t)(b * SEQ + SEQ - 1) * DIM;
    const float* wr = Wh + (size_t)n * DIM;
    float s = 0.f;
    for (int d = tid; d < DIM; d += 128) s += xr[d] * wr[d];
#pragma unroll
    for (int o = 16; o; o >>= 1) s += __shfl_xor_sync(0xffffffffu, s, o);
    __shared__ float red[4];
    if ((tid & 31) == 0) red[tid >> 5] = s;
    __syncthreads();
    if (tid == 0)
        g_hat[b * HAM + n] = red[0] + red[1] + red[2] + red[3] + bh[n];
}

__global__ void loss_kernel(const float* __restrict__ y, const float* __restrict__ w,
                            float* __restrict__ out) {
    int tid = threadIdx.x, lane = tid & 31, warp = tid >> 5;
    float s = 0.f;
    for (int idx = tid; idx < BB * HAM; idx += 256) {
        int b = idx / HAM, j = idx - b * HAM;
        float resid = y[idx] - w[(size_t)(b * 16 + 15) * HAM + j];
        float d = g_hat[idx] - resid;
        s += d * d;
    }
#pragma unroll
    for (int o = 16; o; o >>= 1) s += __shfl_xor_sync(0xffffffffu, s, o);
    __shared__ float red[8];
    if (lane == 0) red[warp] = s;
    __syncthreads();
    if (tid == 0) {
        float t = 0.f;
#pragma unroll
        for (int k = 0; k < 8; k++) t += red[k];
        out[0] = t * (1.f / (BB * HAM));
    }
}

// ------------------------------- launch -------------------------------------
extern "C" void kernel_launch(void* const* d_in, const int* in_sizes, int n_in,
                              void* d_out, int out_size) {
    const float* x      = (const float*)d_in[0];
    const float* w      = (const float*)d_in[1];
    const float* y      = (const float*)d_in[2];
    const float* W_nail = (const float*)d_in[3];
    const float* b_nail = (const float*)d_in[4];
    const float* W_cond = (const float*)d_in[5];
    const float* b_cond = (const float*)d_in[6];
    const float* Wqkv   = (const float*)d_in[7];
    const float* bqkv   = (const float*)d_in[8];
    const float* Wo     = (const float*)d_in[9];
    const float* bo     = (const float*)d_in[10];
    const float* ln1g   = (const float*)d_in[11];
    const float* ln1b   = (const float*)d_in[12];
    const float* ln2g   = (const float*)d_in[13];
    const float* ln2b   = (const float*)d_in[14];
    const float* W1     = (const float*)d_in[15];
    const float* b1     = (const float*)d_in[16];
    const float* W2     = (const float*)d_in[17];
    const float* b2     = (const float*)d_in[18];
    const float* W_ham  = (const float*)d_in[19];
    const float* b_ham  = (const float*)d_in[20];

    void* p;
    bf16 *WqkvH, *WoH, *W1H, *W2H, *tgtH, *qkv, *obuf, *hbuf;
    float *tgt, *x1;
    int* xmask;
    cudaGetSymbolAddress(&p, g_WqkvH); WqkvH = (bf16*)p;
    cudaGetSymbolAddress(&p, g_WoH);   WoH   = (bf16*)p;
    cudaGetSymbolAddress(&p, g_W1H);   W1H   = (bf16*)p;
    cudaGetSymbolAddress(&p, g_W2H);   W2H   = (bf16*)p;
    cudaGetSymbolAddress(&p, g_tgtH);  tgtH  = (bf16*)p;
    cudaGetSymbolAddress(&p, g_qkv);   qkv   = (bf16*)p;
    cudaGetSymbolAddress(&p, g_obuf);  obuf  = (bf16*)p;
    cudaGetSymbolAddress(&p, g_hbuf);  hbuf  = (bf16*)p;
    cudaGetSymbolAddress(&p, g_tgt);   tgt   = (float*)p;
    cudaGetSymbolAddress(&p, g_x1);    x1    = (float*)p;
    cudaGetSymbolAddress(&p, g_xmask); xmask = (int*)p;

    cudaFuncSetAttribute(gemm_tc<2>, cudaFuncAttributeMaxDynamicSharedMemorySize, G_SMEM);
    cudaFuncSetAttribute(gemm_tc<3>, cudaFuncAttributeMaxDynamicSharedMemorySize, G_SMEM);
    cudaFuncSetAttribute(gemm_tc<4>, cudaFuncAttributeMaxDynamicSharedMemorySize, G_SMEM);
    cudaFuncSetAttribute(flash_kernel, cudaFuncAttributeMaxDynamicSharedMemorySize, FA_SMEM);

    // weight conversion fp32 -> bf16 (every launch: deterministic)
    {
        int n;
        n = NLAY * QKVD * DIM / 4; f2h4_kernel<<<(n + 255) / 256, 256>>>((const float4*)Wqkv, (__nv_bfloat162*)WqkvH, n);
        n = NLAY * DIM * DIM / 4;  f2h4_kernel<<<(n + 255) / 256, 256>>>((const float4*)Wo,   (__nv_bfloat162*)WoH,   n);
        n = NLAY * FFD * DIM / 4;  f2h4_kernel<<<(n + 255) / 256, 256>>>((const float4*)W1,   (__nv_bfloat162*)W1H,   n);
        n = NLAY * DIM * FFD / 4;  f2h4_kernel<<<(n + 255) / 256, 256>>>((const float4*)W2,   (__nv_bfloat162*)W2H,   n);
    }

    embed_x_kernel<<<512, 256>>>(x, W_nail, b_nail);
    embed_w_kernel<<<384, 256>>>(w, W_cond, b_cond);

    for (int l = 0; l < NLAY; l++) {
        // QKV projection: (7168x1024)@(3072x1024)^T + bias -> bf16
        gemm_tc<2><<<dim3(QKVD / 128, MTOK / 128), 256, G_SMEM>>>(
            tgtH, WqkvH + (size_t)l * QKVD * DIM, nullptr, qkv,
            bqkv + l * QKVD, nullptr, MTOK, QKVD, DIM);

        // fused attention -> obuf (b, s, h*64+d) bf16
        flash_kernel<<<dim3(SEQ / 128, BB * NH), 256, FA_SMEM>>>(qkv, obuf, xmask);

        // O projection + bias + residual -> fp32 X1
        gemm_tc<3><<<dim3(DIM / 128, MTOK / 128), 256, G_SMEM>>>(
            obuf, WoH + (size_t)l * DIM * DIM, x1, nullptr,
            bo + l * DIM, tgt, MTOK, DIM, DIM);

        ln_kernel<<<MTOK, 256>>>(x1, ln1g + l * DIM, ln1b + l * DIM);

        // FF1 + bias + exact GELU -> bf16
        gemm_tc<4><<<dim3(FFD / 128, MTOK / 128), 256, G_SMEM>>>(
            tgtH, W1H + (size_t)l * FFD * DIM, nullptr, hbuf,
            b1 + l * FFD, nullptr, MTOK, FFD, DIM);

        // FF2 + bias + residual -> fp32 X1
        gemm_tc<3><<<dim3(DIM / 128, MTOK / 128), 256, G_SMEM>>>(
            hbuf, W2H + (size_t)l * DIM * FFD, x1, nullptr,
            b2 + l * DIM, tgt, MTOK, DIM, FFD);

        ln_kernel<<<MTOK, 256>>>(x1, ln2g + l * DIM, ln2b + l * DIM);
    }

    head_kernel<<<dim3(HAM, BB), 128>>>(W_ham, b_ham);
    loss_kernel<<<1, 256>>>(y, w, (float*)d_out);
}

// round 14
// speedup vs baseline: 1.2614x; 1.0003x over previous
#include <cuda_runtime.h>
#include <cuda_bf16.h>
#include <mma.h>
#include <math.h>

using namespace nvcuda;
typedef __nv_bfloat16 bf16;

#define BB   8
#define LXT  512
#define SEQ  896
#define DIM  1024
#define NH   16
#define FFD  4096
#define NLAY 4
#define MTOK (BB*SEQ)          // 7168
#define HAM  144
#define QKVD (3*DIM)           // 3072

// ---------------- static device scratch (no allocations allowed) -------------
__device__ float g_tgt   [(size_t)MTOK*DIM];
__device__ bf16  g_tgtH  [(size_t)MTOK*DIM];
__device__ float g_x1    [(size_t)MTOK*DIM];
__device__ bf16  g_qkv   [(size_t)MTOK*QKVD];
__device__ bf16  g_obuf  [(size_t)MTOK*DIM];
__device__ bf16  g_hbuf  [(size_t)MTOK*FFD];
__device__ bf16  g_WqkvH [(size_t)NLAY*QKVD*DIM];
__device__ bf16  g_WoH   [(size_t)NLAY*DIM*DIM];
__device__ bf16  g_W1H   [(size_t)NLAY*FFD*DIM];
__device__ bf16  g_W2H   [(size_t)NLAY*DIM*FFD];
__device__ int   g_xmask [BB*LXT];
__device__ float g_hat   [BB*HAM];

// ------------------------------- helpers ------------------------------------
__device__ __forceinline__ float gelu_f(float x) {
    return 0.5f * x * (1.f + erff(x * 0.7071067811865476f));
}

__device__ __forceinline__ void cp16(void* dst, const void* src) {
    unsigned d = (unsigned)__cvta_generic_to_shared(dst);
    asm volatile("cp.async.cg.shared.global [%0], [%1], 16;\n" :: "r"(d), "l"(src));
}
#define CP_COMMIT() asm volatile("cp.async.commit_group;\n" ::: "memory")
#define CP_WAIT3()  asm volatile("cp.async.wait_group 3;\n" ::: "memory")

// vectorized fp32 -> bf16
__global__ void f2h4_kernel(const float4* __restrict__ s, __nv_bfloat162* __restrict__ d, int n4) {
    int i = blockIdx.x * blockDim.x + threadIdx.x;
    if (i < n4) {
        float4 v = s[i];
        d[2 * i]     = __floats2bfloat162_rn(v.x, v.y);
        d[2 * i + 1] = __floats2bfloat162_rn(v.z, v.w);
    }
}

// -------------------- embeddings -------------------------------------------
__global__ void embed_x_kernel(const float* __restrict__ x,
                               const float* __restrict__ Wn,
                               const float* __restrict__ bn) {
    const float RSQ = 0.9999500037496876f;           // 1/sqrt(1.0001)
    const float PEC = -6.9077552789821368f / 1024.f; // -ln(1000)/D
    int tok0 = blockIdx.x * 8;
    int tid  = threadIdx.x;
    __shared__ float r[8][64];
    __shared__ float tS[8];
#pragma unroll
    for (int t = 0; t < 2; t++) {
        int idx = tid + t * 256;
        int tk = idx >> 6, f = idx & 63;
        float v = x[(size_t)(tok0 + tk) * 64 + f];
        int nn = isnan(v);
        if (nn) v = 0.f;
        if (f == 0) { tS[tk] = v; g_xmask[tok0 + tk] = nn; }
        float c = v * RSQ;
        r[tk][f] = fminf(fmaxf(c, -5.f), 5.f);
    }
    __syncthreads();
    float acc[4][8];
#pragma unroll
    for (int c = 0; c < 4; c++)
#pragma unroll
        for (int tk = 0; tk < 8; tk++) acc[c][tk] = 0.f;
    for (int k = 0; k < 63; k++) {
        float rv[8];
#pragma unroll
        for (int tk = 0; tk < 8; tk++) rv[tk] = r[tk][k + 1];
#pragma unroll
        for (int c = 0; c < 4; c++) {
            int n = tid + c * 256;
            float wv = Wn[(size_t)n * 63 + k];
#pragma unroll
            for (int tk = 0; tk < 8; tk++) acc[c][tk] += rv[tk] * wv;
        }
    }
#pragma unroll
    for (int c = 0; c < 4; c++) {
        int n = tid + c * 256;
        float bnv = bn[n];
        float div = expf((float)(n >> 1) * PEC);
#pragma unroll
        for (int tk = 0; tk < 8; tk++) {
            int tok = tok0 + tk;
            int b = tok >> 9, s = tok & 511;
            float ang = tS[tk] * div;
            float pe = (n & 1) ? cosf(ang) : sinf(ang);
            float v = acc[c][tk] + bnv + pe;
            size_t o = ((size_t)(b * SEQ + s)) * DIM + n;
            g_tgt[o]  = v;
            g_tgtH[o] = __float2bfloat16(v);
        }
    }
}

__global__ void embed_w_kernel(const float* __restrict__ w,
                               const float* __restrict__ Wc,
                               const float* __restrict__ bc) {
    const float RSQ = 0.9999500037496876f;
    const float PEC = -6.9077552789821368f / 1024.f;
    int g0  = blockIdx.x * 8;   // gidx = b*384 + rr
    int tid = threadIdx.x;
    __shared__ float r[8][6];
    if (tid < 48) {
        int tk = tid / 6, k = tid - tk * 6;
        float v = w[(size_t)(g0 + tk) * 6 + k];
        if (isnan(v)) v = 0.f;
        r[tk][k] = fminf(fmaxf(v * RSQ, -5.f), 5.f);
    }
    __syncthreads();
#pragma unroll
    for (int c = 0; c < 4; c++) {
        int n = tid + c * 256;
        float bcv = bc[n];
        float wv[6];
#pragma unroll
        for (int k = 0; k < 6; k++) wv[k] = Wc[(size_t)n * 6 + k];
        float div = expf((float)(n >> 1) * PEC);
#pragma unroll
        for (int tk = 0; tk < 8; tk++) {
            int g = g0 + tk;
            int b = g / 384, rr = g - b * 384;
            float a = bcv;
#pragma unroll
            for (int k = 0; k < 6; k++) a += r[tk][k] * wv[k];
            float ang = (float)(512 + rr) * div;
            a += (n & 1) ? cosf(ang) : sinf(ang);
            size_t o = ((size_t)(b * SEQ + 512 + rr)) * DIM + n;
            g_tgt[o]  = a;
            g_tgtH[o] = __float2bfloat16(a);
        }
    }
}

// --------- pipelined dense GEMM (C = A @ B^T), 128x128 tile, cp.async x4 -----
// EPI: 2 bf16=acc+bias | 3 f32=acc+bias+resid | 4 bf16=gelu(acc+bias)
// M,N multiples of 128; K multiple of 32. A: MxK ld K, B: NxK ld K, C: MxN.
#define GA_STAGE 10240                       // 128*40*2 bytes
#define GB_BASE  (4*GA_STAGE)
#define G_SMEM   (8*GA_STAGE)                // 81920

template<int EPI>
__global__ void __launch_bounds__(256, 2) gemm_tc(
    const bf16* __restrict__ A, const bf16* __restrict__ B,
    float* __restrict__ Cf, bf16* __restrict__ Ch,
    const float* __restrict__ bias, const float* __restrict__ resid,
    int M, int N, int K) {
    extern __shared__ char raw[];

    int tid  = threadIdx.x;
    int warp = tid >> 5, lane = tid & 31;
    int wm = warp >> 2, wn = warp & 3;          // 2 x 4 warp grid
    int m0 = blockIdx.y * 128, n0 = blockIdx.x * 128;

    wmma::fragment<wmma::accumulator, 16, 16, 16, float> cfr[4][2];
#pragma unroll
    for (int i = 0; i < 4; i++)
#pragma unroll
        for (int j = 0; j < 2; j++) wmma::fill_fragment(cfr[i][j], 0.f);

    // thread's fixed load slots (2 chunks A + 2 chunks B per stage)
    int c0r = (tid) >> 2,        c0k = (tid) & 3;
    int c1r = (tid + 256) >> 2,  c1k = (tid + 256) & 3;
    const bf16* Arow0 = A + (size_t)(m0 + c0r) * K + c0k * 8;
    const bf16* Arow1 = A + (size_t)(m0 + c1r) * K + c1k * 8;
    const bf16* Brow0 = B + (size_t)(n0 + c0r) * K + c0k * 8;
    const bf16* Brow1 = B + (size_t)(n0 + c1r) * K + c1k * 8;
    size_t soA0 = (size_t)c0r * 80 + c0k * 16;
    size_t soA1 = (size_t)c1r * 80 + c1k * 16;

    int KT = K >> 5;
    int fetch = 0;
#pragma unroll
    for (; fetch < 3; fetch++) {
        char* as = raw + fetch * GA_STAGE;
        char* bs = raw + GB_BASE + fetch * GA_STAGE;
        int k0 = fetch * 32;
        cp16(as + soA0, Arow0 + k0);
        cp16(as + soA1, Arow1 + k0);
        cp16(bs + soA0, Brow0 + k0);
        cp16(bs + soA1, Brow1 + k0);
        CP_COMMIT();
    }

    for (int kt = 0; kt < KT; kt++) {
        if (fetch < KT) {
            int s = fetch & 3;
            char* as = raw + s * GA_STAGE;
            char* bs = raw + GB_BASE + s * GA_STAGE;
            int k0 = fetch * 32;
            cp16(as + soA0, Arow0 + k0);
            cp16(as + soA1, Arow1 + k0);
            cp16(bs + soA0, Brow0 + k0);
            cp16(bs + soA1, Brow1 + k0);
            fetch++;
        }
        CP_COMMIT();
        CP_WAIT3();
        __syncthreads();
        bf16 (*As)[40] = (bf16(*)[40])(raw + (kt & 3) * GA_STAGE);
        bf16 (*Bs)[40] = (bf16(*)[40])(raw + GB_BASE + (kt & 3) * GA_STAGE);
#pragma unroll
        for (int ks = 0; ks < 32; ks += 16) {
            wmma::fragment<wmma::matrix_a, 16, 16, 16, bf16, wmma::row_major> af[4];
            wmma::fragment<wmma::matrix_b, 16, 16, 16, bf16, wmma::col_major> bfg[2];
#pragma unroll
            for (int i = 0; i < 4; i++)
                wmma::load_matrix_sync(af[i], &As[wm * 64 + i * 16][ks], 40);
#pragma unroll
            for (int j = 0; j < 2; j++)
                wmma::load_matrix_sync(bfg[j], &Bs[wn * 32 + j * 16][ks], 40);
#pragma unroll
            for (int i = 0; i < 4; i++)
#pragma unroll
                for (int j = 0; j < 2; j++)
                    wmma::mma_sync(cfr[i][j], af[i], bfg[j], cfr[i][j]);
        }
        __syncthreads();
    }

    // epilogue: stage through smem (reuses pipeline buffers, post-sync)
    float* sc = (float*)raw + warp * 256;
#pragma unroll
    for (int i = 0; i < 4; i++) {
#pragma unroll
        for (int j = 0; j < 2; j++) {
            wmma::store_matrix_sync(sc, cfr[i][j], 16, wmma::mem_row_major);
            __syncwarp();
            int r0 = m0 + wm * 64 + i * 16;
            int c0 = n0 + wn * 32 + j * 16;
#pragma unroll
            for (int e = 0; e < 8; e++) {
                int el = e * 32 + lane;
                int rr = el >> 4, cc = el & 15;
                int gr = r0 + rr, gc = c0 + cc;
                float v = sc[el];
                size_t o = (size_t)gr * N + gc;
                if (EPI == 2)      Ch[o] = __float2bfloat16(v + bias[gc]);
                else if (EPI == 3) Cf[o] = v + bias[gc] + resid[o];
                else if (EPI == 4) Ch[o] = __float2bfloat16(gelu_f(v + bias[gc]));
            }
            __syncwarp();
        }
    }
}

// -------------------- fused flash attention ---------------------------------
// grid (7, 128): q-tile of 128 per (b,h). Online softmax, smem-resident O.
#define QS_OFF 0
#define KS_OFF 18432
#define VS_OFF 36864
#define SS_OFF 55296
#define PS_OFF 122880
#define OS_OFF 157696
#define MR_OFF 192512
#define FA_SMEM 193536

__global__ void __launch_bounds__(256) flash_kernel(const bf16* __restrict__ qkv,
                                                    bf16* __restrict__ obuf,
                                                    const int* __restrict__ xmask) {
    extern __shared__ char raw[];
    bf16  (*Qs)[72]  = (bf16(*)[72]) (raw + QS_OFF);
    bf16  (*Ks)[72]  = (bf16(*)[72]) (raw + KS_OFF);
    bf16  (*Vs)[72]  = (bf16(*)[72]) (raw + VS_OFF);
    float (*Ss)[132] = (float(*)[132])(raw + SS_OFF);
    bf16  (*Ps)[136] = (bf16(*)[136])(raw + PS_OFF);
    float (*Os)[68]  = (float(*)[68]) (raw + OS_OFF);
    float* mrow = (float*)(raw + MR_OFF);
    float* lrow = mrow + 128;

    int z = blockIdx.y;
    int b = z >> 4, h = z & 15;
    int qi = blockIdx.x, q0 = qi * 128;
    int tid = threadIdx.x, warp = tid >> 5, lane = tid & 31;
    int wm = warp >> 2, wn = warp & 3;

    const bf16* Qg = qkv + (size_t)(b * SEQ) * QKVD + h * 64;
    const bf16* Kg = Qg + DIM;
    const bf16* Vg = Qg + 2 * DIM;

    // load Q tile (128 x 64), init O, m, l
#pragma unroll
    for (int t = 0; t < 4; t++) {
        int c = tid + t * 256;
        int row = c >> 3, kc = c & 7;
        *(int4*)&Qs[row][kc * 8] = *(const int4*)(Qg + (size_t)(q0 + row) * QKVD + kc * 8);
    }
#pragma unroll
    for (int t = 0; t < 32; t++) {
        int idx = tid + t * 256;
        Os[idx >> 6][idx & 63] = 0.f;
    }
    if (tid < 128) { mrow[tid] = -1e30f; lrow[tid] = 0.f; }
    __syncthreads();

    int ktmax = (qi > 3) ? qi : 3;
    for (int kt = 0; kt <= ktmax; kt++) {
        // load K, V tiles
#pragma unroll
        for (int t = 0; t < 4; t++) {
            int c = tid + t * 256;
            int row = c >> 3, kc = c & 7;
            size_t go = (size_t)(kt * 128 + row) * QKVD + kc * 8;
            *(int4*)&Ks[row][kc * 8] = *(const int4*)(Kg + go);
            *(int4*)&Vs[row][kc * 8] = *(const int4*)(Vg + go);
        }
        __syncthreads();

        // S = Q @ K^T  (128x128, k=64)
        {
            wmma::fragment<wmma::accumulator, 16, 16, 16, float> sf[4][2];
#pragma unroll
            for (int i = 0; i < 4; i++)
#pragma unroll
                for (int j = 0; j < 2; j++) wmma::fill_fragment(sf[i][j], 0.f);
#pragma unroll
            for (int ks = 0; ks < 4; ks++) {
                wmma::fragment<wmma::matrix_a, 16, 16, 16, bf16, wmma::row_major> af[4];
                wmma::fragment<wmma::matrix_b, 16, 16, 16, bf16, wmma::col_major> bfg[2];
#pragma unroll
                for (int i = 0; i < 4; i++)
                    wmma::load_matrix_sync(af[i], &Qs[wm * 64 + i * 16][ks * 16], 72);
#pragma unroll
                for (int j = 0; j < 2; j++)
                    wmma::load_matrix_sync(bfg[j], &Ks[wn * 32 + j * 16][ks * 16], 72);
#pragma unroll
                for (int i = 0; i < 4; i++)
#pragma unroll
                    for (int j = 0; j < 2; j++)
                        wmma::mma_sync(sf[i][j], af[i], bfg[j], sf[i][j]);
            }
#pragma unroll
            for (int i = 0; i < 4; i++)
#pragma unroll
                for (int j = 0; j < 2; j++)
                    wmma::store_matrix_sync(&Ss[wm * 64 + i * 16][wn * 32 + j * 16],
                                            sf[i][j], 132, wmma::mem_row_major);
        }
        __syncthreads();

        // online softmax on rows warp*16 .. warp*16+15
        {
            int jbase = kt * 128 + lane;
            bool xval[4];
            if (kt < 4) {
#pragma unroll
                for (int t = 0; t < 4; t++)
                    xval[t] = (xmask[b * LXT + jbase + 32 * t] == 0);
            }
#pragma unroll 1
            for (int rr = 0; rr < 16; rr++) {
                int r = warp * 16 + rr;
                int ig = q0 + r;
                float v[4]; bool val[4];
                float mx = -1e30f;
#pragma unroll
                for (int t = 0; t < 4; t++) {
                    int jg = jbase + 32 * t;
                    bool valid = (kt < 4) ? xval[t] : (jg <= ig);
                    float s = valid ? Ss[r][lane + 32 * t] * 0.125f : -1e30f;
                    val[t] = valid; v[t] = s;
                    mx = fmaxf(mx, s);
                }
#pragma unroll
                for (int o = 16; o; o >>= 1) mx = fmaxf(mx, __shfl_xor_sync(0xffffffffu, mx, o));
                float mo = mrow[r];
                float mn = fmaxf(mo, mx);
                float sum = 0.f;
#pragma unroll
                for (int t = 0; t < 4; t++) {
                    float e = val[t] ? __expf(v[t] - mn) : 0.f;
                    Ps[r][lane + 32 * t] = __float2bfloat16(e);
                    sum += e;
                }
#pragma unroll
                for (int o = 16; o; o >>= 1) sum += __shfl_xor_sync(0xffffffffu, sum, o);
                float c = __expf(mo - mn);
                Os[r][lane]      *= c;
                Os[r][lane + 32] *= c;
                if (lane == 0) { mrow[r] = mn; lrow[r] = lrow[r] * c + sum; }
            }
        }
        // (no sync needed: PV uses only this warp's rows of Ps/Os, plus Vs)

        // O += P @ V  (rows warp*16..+15, n=64, k=128)
        {
            int r0 = warp * 16;
            wmma::fragment<wmma::accumulator, 16, 16, 16, float> of[4];
#pragma unroll
            for (int n = 0; n < 4; n++)
                wmma::load_matrix_sync(of[n], &Os[r0][n * 16], 68, wmma::mem_row_major);
#pragma unroll
            for (int ks = 0; ks < 8; ks++) {
                wmma::fragment<wmma::matrix_a, 16, 16, 16, bf16, wmma::row_major> af;
                wmma::load_matrix_sync(af, &Ps[r0][ks * 16], 136);
#pragma unroll
                for (int n = 0; n < 4; n++) {
                    wmma::fragment<wmma::matrix_b, 16, 16, 16, bf16, wmma::row_major> bfg;
                    wmma::load_matrix_sync(bfg, &Vs[ks * 16][n * 16], 72);
                    wmma::mma_sync(of[n], af, bfg, of[n]);
                }
            }
#pragma unroll
            for (int n = 0; n < 4; n++)
                wmma::store_matrix_sync(&Os[r0][n * 16], of[n], 68, wmma::mem_row_major);
        }
        __syncthreads();
    }

    // write O / l -> obuf (b, s, h*64 + d) bf16
#pragma unroll
    for (int t = 0; t < 32; t++) {
        int idx = tid + t * 256;
        int r = idx >> 6, d = idx & 63;
        float v = Os[r][d] / lrow[r];
        obuf[(size_t)(b * SEQ + q0 + r) * DIM + h * 64 + d] = __float2bfloat16(v);
    }
}

// --------------------------- LayerNorm --------------------------------------
__global__ void ln_kernel(const float* __restrict__ X, const float* __restrict__ g,
                          const float* __restrict__ bsh) {
    int row = blockIdx.x;
    int tid = threadIdx.x, lane = tid & 31, warp = tid >> 5;
    const float* xr = X + (size_t)row * DIM;
    float s = 0.f, s2 = 0.f;
#pragma unroll
    for (int t = 0; t < 4; t++) {
        float v = xr[tid + t * 256];
        s += v; s2 += v * v;
    }
    __shared__ float rs[8], rs2[8];
#pragma unroll
    for (int o = 16; o; o >>= 1) {
        s  += __shfl_xor_sync(0xffffffffu, s, o);
        s2 += __shfl_xor_sync(0xffffffffu, s2, o);
    }
    if (lane == 0) { rs[warp] = s; rs2[warp] = s2; }
    __syncthreads();
    float ts = 0.f, ts2 = 0.f;
#pragma unroll
    for (int k = 0; k < 8; k++) { ts += rs[k]; ts2 += rs2[k]; }
    float mean = ts * (1.f / DIM);
    float var  = ts2 * (1.f / DIM) - mean * mean;
    float inv  = rsqrtf(var + 1e-5f);
#pragma unroll
    for (int t = 0; t < 4; t++) {
        int i = tid + t * 256;
        float v = (xr[i] - mean) * inv * g[i] + bsh[i];
        size_t o = (size_t)row * DIM + i;
        g_tgt[o]  = v;
        g_tgtH[o] = __float2bfloat16(v);
    }
}

// --------------------------- output head + loss -----------------------------
__global__ void head_kernel(const float* __restrict__ Wh, const float* __restrict__ bh) {
    int n = blockIdx.x, b = blockIdx.y;
    int tid = threadIdx.x;
    const float* xr = g_tgt + (size_t)(b * SEQ + SEQ - 1) * DIM;
    const float* wr = Wh + (size_t)n * DIM;
    float s = 0.f;
    for (int d = tid; d < DIM; d += 128) s += xr[d] * wr[d];
#pragma unroll
    for (int o = 16; o; o >>= 1) s += __shfl_xor_sync(0xffffffffu, s, o);
    __shared__ float red[4];
    if ((tid & 31) == 0) red[tid >> 5] = s;
    __syncthreads();
    if (tid == 0)
        g_hat[b * HAM + n] = red[0] + red[1] + red[2] + red[3] + bh[n];
}

__global__ void loss_kernel(const float* __restrict__ y, const float* __restrict__ w,
                            float* __restrict__ out) {
    int tid = threadIdx.x, lane = tid & 31, warp = tid >> 5;
    float s = 0.f;
    for (int idx = tid; idx < BB * HAM; idx += 256) {
        int b = idx / HAM, j = idx - b * HAM;
        float resid = y[idx] - w[(size_t)(b * 16 + 15) * HAM + j];
        float d = g_hat[idx] - resid;
        s += d * d;
    }
#pragma unroll
    for (int o = 16; o; o >>= 1) s += __shfl_xor_sync(0xffffffffu, s, o);
    __shared__ float red[8];
    if (lane == 0) red[warp] = s;
    __syncthreads();
    if (tid == 0) {
        float t = 0.f;
#pragma unroll
        for (int k = 0; k < 8; k++) t += red[k];
        out[0] = t * (1.f / (BB * HAM));
    }
}

// ------------------------------- launch -------------------------------------
extern "C" void kernel_launch(void* const* d_in, const int* in_sizes, int n_in,
                              void* d_out, int out_size) {
    const float* x      = (const float*)d_in[0];
    const float* w      = (const float*)d_in[1];
    const float* y      = (const float*)d_in[2];
    const float* W_nail = (const float*)d_in[3];
    const float* b_nail = (const float*)d_in[4];
    const float* W_cond = (const float*)d_in[5];
    const float* b_cond = (const float*)d_in[6];
    const float* Wqkv   = (const float*)d_in[7];
    const float* bqkv   = (const float*)d_in[8];
    const float* Wo     = (const float*)d_in[9];
    const float* bo     = (const float*)d_in[10];
    const float* ln1g   = (const float*)d_in[11];
    const float* ln1b   = (const float*)d_in[12];
    const float* ln2g   = (const float*)d_in[13];
    const float* ln2b   = (const float*)d_in[14];
    const float* W1     = (const float*)d_in[15];
    const float* b1     = (const float*)d_in[16];
    const float* W2     = (const float*)d_in[17];
    const float* b2     = (const float*)d_in[18];
    const float* W_ham  = (const float*)d_in[19];
    const float* b_ham  = (const float*)d_in[20];

    void* p;
    bf16 *WqkvH, *WoH, *W1H, *W2H, *tgtH, *qkv, *obuf, *hbuf;
    float *tgt, *x1;
    int* xmask;
    cudaGetSymbolAddress(&p, g_WqkvH); WqkvH = (bf16*)p;
    cudaGetSymbolAddress(&p, g_WoH);   WoH   = (bf16*)p;
    cudaGetSymbolAddress(&p, g_W1H);   W1H   = (bf16*)p;
    cudaGetSymbolAddress(&p, g_W2H);   W2H   = (bf16*)p;
    cudaGetSymbolAddress(&p, g_tgtH);  tgtH  = (bf16*)p;
    cudaGetSymbolAddress(&p, g_qkv);   qkv   = (bf16*)p;
    cudaGetSymbolAddress(&p, g_obuf);  obuf  = (bf16*)p;
    cudaGetSymbolAddress(&p, g_hbuf);  hbuf  = (bf16*)p;
    cudaGetSymbolAddress(&p, g_tgt);   tgt   = (float*)p;
    cudaGetSymbolAddress(&p, g_x1);    x1    = (float*)p;
    cudaGetSymbolAddress(&p, g_xmask); xmask = (int*)p;

    cudaFuncSetAttribute(gemm_tc<2>, cudaFuncAttributeMaxDynamicSharedMemorySize, G_SMEM);
    cudaFuncSetAttribute(gemm_tc<3>, cudaFuncAttributeMaxDynamicSharedMemorySize, G_SMEM);
    cudaFuncSetAttribute(gemm_tc<4>, cudaFuncAttributeMaxDynamicSharedMemorySize, G_SMEM);
    cudaFuncSetAttribute(flash_kernel, cudaFuncAttributeMaxDynamicSharedMemorySize, FA_SMEM);

    // weight conversion fp32 -> bf16 (every launch: deterministic)
    {
        int n;
        n = NLAY * QKVD * DIM / 4; f2h4_kernel<<<(n + 255) / 256, 256>>>((const float4*)Wqkv, (__nv_bfloat162*)WqkvH, n);
        n = NLAY * DIM * DIM / 4;  f2h4_kernel<<<(n + 255) / 256, 256>>>((const float4*)Wo,   (__nv_bfloat162*)WoH,   n);
        n = NLAY * FFD * DIM / 4;  f2h4_kernel<<<(n + 255) / 256, 256>>>((const float4*)W1,   (__nv_bfloat162*)W1H,   n);
        n = NLAY * DIM * FFD / 4;  f2h4_kernel<<<(n + 255) / 256, 256>>>((const float4*)W2,   (__nv_bfloat162*)W2H,   n);
    }

    embed_x_kernel<<<512, 256>>>(x, W_nail, b_nail);
    embed_w_kernel<<<384, 256>>>(w, W_cond, b_cond);

    for (int l = 0; l < NLAY; l++) {
        // QKV projection: (7168x1024)@(3072x1024)^T + bias -> bf16
        gemm_tc<2><<<dim3(QKVD / 128, MTOK / 128), 256, G_SMEM>>>(
            tgtH, WqkvH + (size_t)l * QKVD * DIM, nullptr, qkv,
            bqkv + l * QKVD, nullptr, MTOK, QKVD, DIM);

        // fused attention -> obuf (b, s, h*64+d) bf16
        flash_kernel<<<dim3(SEQ / 128, BB * NH), 256, FA_SMEM>>>(qkv, obuf, xmask);

        // O projection + bias + residual -> fp32 X1
        gemm_tc<3><<<dim3(DIM / 128, MTOK / 128), 256, G_SMEM>>>(
            obuf, WoH + (size_t)l * DIM * DIM, x1, nullptr,
            bo + l * DIM, tgt, MTOK, DIM, DIM);

        ln_kernel<<<MTOK, 256>>>(x1, ln1g + l * DIM, ln1b + l * DIM);

        // FF1 + bias + exact GELU -> bf16
        gemm_tc<4><<<dim3(FFD / 128, MTOK / 128), 256, G_SMEM>>>(
            tgtH, W1H + (size_t)l * FFD * DIM, nullptr, hbuf,
            b1 + l * FFD, nullptr, MTOK, FFD, DIM);

        // FF2 + bias + residual -> fp32 X1
        gemm_tc<3><<<dim3(DIM / 128, MTOK / 128), 256, G_SMEM>>>(
            hbuf, W2H + (size_t)l * DIM * FFD, x1, nullptr,
            b2 + l * DIM, tgt, MTOK, DIM, FFD);

        ln_kernel<<<MTOK, 256>>>(x1, ln2g + l * DIM, ln2b + l * DIM);
    }

    head_kernel<<<dim3(HAM, BB), 128>>>(W_ham, b_ham);
    loss_kernel<<<1, 256>>>(y, w, (float*)d_out);
}

// round 15
// speedup vs baseline: 1.3712x; 1.0871x over previous
#include <cuda_runtime.h>
#include <cuda_bf16.h>
#include <mma.h>
#include <math.h>

using namespace nvcuda;
typedef __nv_bfloat16 bf16;

#define BB   8
#define LXT  512
#define SEQ  896
#define DIM  1024
#define NH   16
#define FFD  4096
#define NLAY 4
#define MTOK (BB*SEQ)          // 7168
#define HAM  144
#define QKVD (3*DIM)           // 3072

// ---------------- static device scratch (no allocations allowed) -------------
__device__ float g_tgt   [(size_t)MTOK*DIM];
__device__ bf16  g_tgtH  [(size_t)MTOK*DIM];
__device__ float g_x1    [(size_t)MTOK*DIM];
__device__ bf16  g_qkv   [(size_t)MTOK*QKVD];
__device__ bf16  g_obuf  [(size_t)MTOK*DIM];
__device__ bf16  g_hbuf  [(size_t)MTOK*FFD];
__device__ bf16  g_WqkvH [(size_t)NLAY*QKVD*DIM];
__device__ bf16  g_WoH   [(size_t)NLAY*DIM*DIM];
__device__ bf16  g_W1H   [(size_t)NLAY*FFD*DIM];
__device__ bf16  g_W2H   [(size_t)NLAY*DIM*FFD];
__device__ int   g_xmask [BB*LXT];
__device__ float g_hat   [BB*HAM];

// ------------------------------- helpers ------------------------------------
__device__ __forceinline__ float gelu_f(float x) {
    return 0.5f * x * (1.f + erff(x * 0.7071067811865476f));
}

__device__ __forceinline__ void cp16(void* dst, const void* src) {
    unsigned d = (unsigned)__cvta_generic_to_shared(dst);
    asm volatile("cp.async.cg.shared.global [%0], [%1], 16;\n" :: "r"(d), "l"(src));
}
#define CP_COMMIT() asm volatile("cp.async.commit_group;\n" ::: "memory")
#define CP_WAIT2()  asm volatile("cp.async.wait_group 2;\n" ::: "memory")

// vectorized fp32 -> bf16
__global__ void f2h4_kernel(const float4* __restrict__ s, __nv_bfloat162* __restrict__ d, int n4) {
    int i = blockIdx.x * blockDim.x + threadIdx.x;
    if (i < n4) {
        float4 v = s[i];
        d[2 * i]     = __floats2bfloat162_rn(v.x, v.y);
        d[2 * i + 1] = __floats2bfloat162_rn(v.z, v.w);
    }
}

// -------------------- embeddings -------------------------------------------
__global__ void embed_x_kernel(const float* __restrict__ x,
                               const float* __restrict__ Wn,
                               const float* __restrict__ bn) {
    const float RSQ = 0.9999500037496876f;           // 1/sqrt(1.0001)
    const float PEC = -6.9077552789821368f / 1024.f; // -ln(1000)/D
    int tok0 = blockIdx.x * 8;
    int tid  = threadIdx.x;
    __shared__ float r[8][64];
    __shared__ float tS[8];
#pragma unroll
    for (int t = 0; t < 2; t++) {
        int idx = tid + t * 256;
        int tk = idx >> 6, f = idx & 63;
        float v = x[(size_t)(tok0 + tk) * 64 + f];
        int nn = isnan(v);
        if (nn) v = 0.f;
        if (f == 0) { tS[tk] = v; g_xmask[tok0 + tk] = nn; }
        float c = v * RSQ;
        r[tk][f] = fminf(fmaxf(c, -5.f), 5.f);
    }
    __syncthreads();
    float acc[4][8];
#pragma unroll
    for (int c = 0; c < 4; c++)
#pragma unroll
        for (int tk = 0; tk < 8; tk++) acc[c][tk] = 0.f;
    for (int k = 0; k < 63; k++) {
        float rv[8];
#pragma unroll
        for (int tk = 0; tk < 8; tk++) rv[tk] = r[tk][k + 1];
#pragma unroll
        for (int c = 0; c < 4; c++) {
            int n = tid + c * 256;
            float wv = Wn[(size_t)n * 63 + k];
#pragma unroll
            for (int tk = 0; tk < 8; tk++) acc[c][tk] += rv[tk] * wv;
        }
    }
#pragma unroll
    for (int c = 0; c < 4; c++) {
        int n = tid + c * 256;
        float bnv = bn[n];
        float div = expf((float)(n >> 1) * PEC);
#pragma unroll
        for (int tk = 0; tk < 8; tk++) {
            int tok = tok0 + tk;
            int b = tok >> 9, s = tok & 511;
            float ang = tS[tk] * div;
            float pe = (n & 1) ? cosf(ang) : sinf(ang);
            float v = acc[c][tk] + bnv + pe;
            size_t o = ((size_t)(b * SEQ + s)) * DIM + n;
            g_tgt[o]  = v;
            g_tgtH[o] = __float2bfloat16(v);
        }
    }
}

__global__ void embed_w_kernel(const float* __restrict__ w,
                               const float* __restrict__ Wc,
                               const float* __restrict__ bc) {
    const float RSQ = 0.9999500037496876f;
    const float PEC = -6.9077552789821368f / 1024.f;
    int g0  = blockIdx.x * 8;   // gidx = b*384 + rr
    int tid = threadIdx.x;
    __shared__ float r[8][6];
    if (tid < 48) {
        int tk = tid / 6, k = tid - tk * 6;
        float v = w[(size_t)(g0 + tk) * 6 + k];
        if (isnan(v)) v = 0.f;
        r[tk][k] = fminf(fmaxf(v * RSQ, -5.f), 5.f);
    }
    __syncthreads();
#pragma unroll
    for (int c = 0; c < 4; c++) {
        int n = tid + c * 256;
        float bcv = bc[n];
        float wv[6];
#pragma unroll
        for (int k = 0; k < 6; k++) wv[k] = Wc[(size_t)n * 6 + k];
        float div = expf((float)(n >> 1) * PEC);
#pragma unroll
        for (int tk = 0; tk < 8; tk++) {
            int g = g0 + tk;
            int b = g / 384, rr = g - b * 384;
            float a = bcv;
#pragma unroll
            for (int k = 0; k < 6; k++) a += r[tk][k] * wv[k];
            float ang = (float)(512 + rr) * div;
            a += (n & 1) ? cosf(ang) : sinf(ang);
            size_t o = ((size_t)(b * SEQ + 512 + rr)) * DIM + n;
            g_tgt[o]  = a;
            g_tgtH[o] = __float2bfloat16(a);
        }
    }
}

// --------- pipelined dense GEMM (C = A @ B^T), 128x128 tile, 4 warps ---------
// Each warp computes a 64x64 register tile (4x4 accum frags).
// 4 cp.async stages, ONE __syncthreads per 32-K iteration.
// EPI: 2 bf16=acc+bias | 3 f32=acc+bias+resid | 4 bf16=gelu(acc+bias)
#define GA_STAGE 10240                       // 128 rows * 40 elems * 2B
#define GB_BASE  (4*GA_STAGE)
#define G_SMEM   (8*GA_STAGE)                // 81920

template<int EPI>
__global__ void __launch_bounds__(128) gemm_tc(
    const bf16* __restrict__ A, const bf16* __restrict__ B,
    float* __restrict__ Cf, bf16* __restrict__ Ch,
    const float* __restrict__ bias, const float* __restrict__ resid,
    int M, int N, int K) {
    extern __shared__ char raw[];

    int tid  = threadIdx.x;
    int warp = tid >> 5, lane = tid & 31;
    int wm = warp >> 1, wn = warp & 1;          // 2 x 2 warp grid, 64x64 each
    int m0 = blockIdx.y * 128, n0 = blockIdx.x * 128;

    wmma::fragment<wmma::accumulator, 16, 16, 16, float> cfr[4][4];
#pragma unroll
    for (int i = 0; i < 4; i++)
#pragma unroll
        for (int j = 0; j < 4; j++) wmma::fill_fragment(cfr[i][j], 0.f);

    // per-thread load slots: 4 chunks A + 4 chunks B per stage (chunk = int4)
    int rrow[4], rkc[4];
    const bf16 *Ap[4], *Bp[4];
    size_t so[4];
#pragma unroll
    for (int t = 0; t < 4; t++) {
        int c = tid + t * 128;
        rrow[t] = c >> 2; rkc[t] = c & 3;
        Ap[t] = A + (size_t)(m0 + rrow[t]) * K + rkc[t] * 8;
        Bp[t] = B + (size_t)(n0 + rrow[t]) * K + rkc[t] * 8;
        so[t] = (size_t)rrow[t] * 80 + rkc[t] * 16;
    }

    int KT = K >> 5;
    int fetch = 0;
#pragma unroll
    for (; fetch < 3; fetch++) {
        char* as = raw + fetch * GA_STAGE;
        char* bs = raw + GB_BASE + fetch * GA_STAGE;
        int k0 = fetch * 32;
#pragma unroll
        for (int t = 0; t < 4; t++) {
            cp16(as + so[t], Ap[t] + k0);
            cp16(bs + so[t], Bp[t] + k0);
        }
        CP_COMMIT();
    }

    for (int kt = 0; kt < KT; kt++) {
        CP_WAIT2();          // stage kt resident
        __syncthreads();     // all warps done with stage kt-1 -> slot reuse safe
        if (fetch < KT) {
            int s = fetch & 3;
            char* as = raw + s * GA_STAGE;
            char* bs = raw + GB_BASE + s * GA_STAGE;
            int k0 = fetch * 32;
#pragma unroll
            for (int t = 0; t < 4; t++) {
                cp16(as + so[t], Ap[t] + k0);
                cp16(bs + so[t], Bp[t] + k0);
            }
            fetch++;
        }
        CP_COMMIT();

        bf16 (*As)[40] = (bf16(*)[40])(raw + (kt & 3) * GA_STAGE);
        bf16 (*Bs)[40] = (bf16(*)[40])(raw + GB_BASE + (kt & 3) * GA_STAGE);
#pragma unroll
        for (int ks = 0; ks < 32; ks += 16) {
            wmma::fragment<wmma::matrix_a, 16, 16, 16, bf16, wmma::row_major> af[4];
            wmma::fragment<wmma::matrix_b, 16, 16, 16, bf16, wmma::col_major> bfg[4];
#pragma unroll
            for (int i = 0; i < 4; i++)
                wmma::load_matrix_sync(af[i], &As[wm * 64 + i * 16][ks], 40);
#pragma unroll
            for (int j = 0; j < 4; j++)
                wmma::load_matrix_sync(bfg[j], &Bs[wn * 64 + j * 16][ks], 40);
#pragma unroll
            for (int i = 0; i < 4; i++)
#pragma unroll
                for (int j = 0; j < 4; j++)
                    wmma::mma_sync(cfr[i][j], af[i], bfg[j], cfr[i][j]);
        }
    }
    __syncthreads();   // all mma reads done before smem reuse in epilogue

    // epilogue: stage each 16x16 fragment through smem
    float* sc = (float*)raw + warp * 256;
#pragma unroll
    for (int i = 0; i < 4; i++) {
#pragma unroll
        for (int j = 0; j < 4; j++) {
            wmma::store_matrix_sync(sc, cfr[i][j], 16, wmma::mem_row_major);
            __syncwarp();
            int r0 = m0 + wm * 64 + i * 16;
            int c0 = n0 + wn * 64 + j * 16;
#pragma unroll
            for (int e = 0; e < 8; e++) {
                int el = e * 32 + lane;
                int rr = el >> 4, cc = el & 15;
                int gr = r0 + rr, gc = c0 + cc;
                float v = sc[el];
                size_t o = (size_t)gr * N + gc;
                if (EPI == 2)      Ch[o] = __float2bfloat16(v + bias[gc]);
                else if (EPI == 3) Cf[o] = v + bias[gc] + resid[o];
                else if (EPI == 4) Ch[o] = __float2bfloat16(gelu_f(v + bias[gc]));
            }
            __syncwarp();
        }
    }
}

// -------------------- fused flash attention ---------------------------------
// grid (7, 128): q-tile of 128 per (b,h). Online softmax, smem-resident O.
#define QS_OFF 0
#define KS_OFF 18432
#define VS_OFF 36864
#define SS_OFF 55296
#define PS_OFF 122880
#define OS_OFF 157696
#define MR_OFF 192512
#define FA_SMEM 193536

__global__ void __launch_bounds__(256) flash_kernel(const bf16* __restrict__ qkv,
                                                    bf16* __restrict__ obuf,
                                                    const int* __restrict__ xmask) {
    extern __shared__ char raw[];
    bf16  (*Qs)[72]  = (bf16(*)[72]) (raw + QS_OFF);
    bf16  (*Ks)[72]  = (bf16(*)[72]) (raw + KS_OFF);
    bf16  (*Vs)[72]  = (bf16(*)[72]) (raw + VS_OFF);
    float (*Ss)[132] = (float(*)[132])(raw + SS_OFF);
    bf16  (*Ps)[136] = (bf16(*)[136])(raw + PS_OFF);
    float (*Os)[68]  = (float(*)[68]) (raw + OS_OFF);
    float* mrow = (float*)(raw + MR_OFF);
    float* lrow = mrow + 128;

    int z = blockIdx.y;
    int b = z >> 4, h = z & 15;
    int qi = blockIdx.x, q0 = qi * 128;
    int tid = threadIdx.x, warp = tid >> 5, lane = tid & 31;
    int wm = warp >> 2, wn = warp & 3;

    const bf16* Qg = qkv + (size_t)(b * SEQ) * QKVD + h * 64;
    const bf16* Kg = Qg + DIM;
    const bf16* Vg = Qg + 2 * DIM;

    // load Q tile (128 x 64), init O, m, l
#pragma unroll
    for (int t = 0; t < 4; t++) {
        int c = tid + t * 256;
        int row = c >> 3, kc = c & 7;
        *(int4*)&Qs[row][kc * 8] = *(const int4*)(Qg + (size_t)(q0 + row) * QKVD + kc * 8);
    }
#pragma unroll
    for (int t = 0; t < 32; t++) {
        int idx = tid + t * 256;
        Os[idx >> 6][idx & 63] = 0.f;
    }
    if (tid < 128) { mrow[tid] = -1e30f; lrow[tid] = 0.f; }
    __syncthreads();

    int ktmax = (qi > 3) ? qi : 3;
    for (int kt = 0; kt <= ktmax; kt++) {
        // load K, V tiles
#pragma unroll
        for (int t = 0; t < 4; t++) {
            int c = tid + t * 256;
            int row = c >> 3, kc = c & 7;
            size_t go = (size_t)(kt * 128 + row) * QKVD + kc * 8;
            *(int4*)&Ks[row][kc * 8] = *(const int4*)(Kg + go);
            *(int4*)&Vs[row][kc * 8] = *(const int4*)(Vg + go);
        }
        __syncthreads();

        // S = Q @ K^T  (128x128, k=64)
        {
            wmma::fragment<wmma::accumulator, 16, 16, 16, float> sf[4][2];
#pragma unroll
            for (int i = 0; i < 4; i++)
#pragma unroll
                for (int j = 0; j < 2; j++) wmma::fill_fragment(sf[i][j], 0.f);
#pragma unroll
            for (int ks = 0; ks < 4; ks++) {
                wmma::fragment<wmma::matrix_a, 16, 16, 16, bf16, wmma::row_major> af[4];
                wmma::fragment<wmma::matrix_b, 16, 16, 16, bf16, wmma::col_major> bfg[2];
#pragma unroll
                for (int i = 0; i < 4; i++)
                    wmma::load_matrix_sync(af[i], &Qs[wm * 64 + i * 16][ks * 16], 72);
#pragma unroll
                for (int j = 0; j < 2; j++)
                    wmma::load_matrix_sync(bfg[j], &Ks[wn * 32 + j * 16][ks * 16], 72);
#pragma unroll
                for (int i = 0; i < 4; i++)
#pragma unroll
                    for (int j = 0; j < 2; j++)
                        wmma::mma_sync(sf[i][j], af[i], bfg[j], sf[i][j]);
            }
#pragma unroll
            for (int i = 0; i < 4; i++)
#pragma unroll
                for (int j = 0; j < 2; j++)
                    wmma::store_matrix_sync(&Ss[wm * 64 + i * 16][wn * 32 + j * 16],
                                            sf[i][j], 132, wmma::mem_row_major);
        }
        __syncthreads();

        // online softmax on rows warp*16 .. warp*16+15
        {
            int jbase = kt * 128 + lane;
            bool xval[4];
            if (kt < 4) {
#pragma unroll
                for (int t = 0; t < 4; t++)
                    xval[t] = (xmask[b * LXT + jbase + 32 * t] == 0);
            }
#pragma unroll 1
            for (int rr = 0; rr < 16; rr++) {
                int r = warp * 16 + rr;
                int ig = q0 + r;
                float v[4]; bool val[4];
                float mx = -1e30f;
#pragma unroll
                for (int t = 0; t < 4; t++) {
                    int jg = jbase + 32 * t;
                    bool valid = (kt < 4) ? xval[t] : (jg <= ig);
                    float s = valid ? Ss[r][lane + 32 * t] * 0.125f : -1e30f;
                    val[t] = valid; v[t] = s;
                    mx = fmaxf(mx, s);
                }
#pragma unroll
                for (int o = 16; o; o >>= 1) mx = fmaxf(mx, __shfl_xor_sync(0xffffffffu, mx, o));
                float mo = mrow[r];
                float mn = fmaxf(mo, mx);
                float sum = 0.f;
#pragma unroll
                for (int t = 0; t < 4; t++) {
                    float e = val[t] ? __expf(v[t] - mn) : 0.f;
                    Ps[r][lane + 32 * t] = __float2bfloat16(e);
                    sum += e;
                }
#pragma unroll
                for (int o = 16; o; o >>= 1) sum += __shfl_xor_sync(0xffffffffu, sum, o);
                float c = __expf(mo - mn);
                Os[r][lane]      *= c;
                Os[r][lane + 32] *= c;
                if (lane == 0) { mrow[r] = mn; lrow[r] = lrow[r] * c + sum; }
            }
        }
        // (no sync needed: PV uses only this warp's rows of Ps/Os, plus Vs)

        // O += P @ V  (rows warp*16..+15, n=64, k=128)
        {
            int r0 = warp * 16;
            wmma::fragment<wmma::accumulator, 16, 16, 16, float> of[4];
#pragma unroll
            for (int n = 0; n < 4; n++)
                wmma::load_matrix_sync(of[n], &Os[r0][n * 16], 68, wmma::mem_row_major);
#pragma unroll
            for (int ks = 0; ks < 8; ks++) {
                wmma::fragment<wmma::matrix_a, 16, 16, 16, bf16, wmma::row_major> af;
                wmma::load_matrix_sync(af, &Ps[r0][ks * 16], 136);
#pragma unroll
                for (int n = 0; n < 4; n++) {
                    wmma::fragment<wmma::matrix_b, 16, 16, 16, bf16, wmma::row_major> bfg;
                    wmma::load_matrix_sync(bfg, &Vs[ks * 16][n * 16], 72);
                    wmma::mma_sync(of[n], af, bfg, of[n]);
                }
            }
#pragma unroll
            for (int n = 0; n < 4; n++)
                wmma::store_matrix_sync(&Os[r0][n * 16], of[n], 68, wmma::mem_row_major);
        }
        __syncthreads();
    }

    // write O / l -> obuf (b, s, h*64 + d) bf16
#pragma unroll
    for (int t = 0; t < 32; t++) {
        int idx = tid + t * 256;
        int r = idx >> 6, d = idx & 63;
        float v = Os[r][d] / lrow[r];
        obuf[(size_t)(b * SEQ + q0 + r) * DIM + h * 64 + d] = __float2bfloat16(v);
    }
}

// --------------------------- LayerNorm (vectorized) --------------------------
__global__ void ln_kernel(const float* __restrict__ X, const float* __restrict__ g,
                          const float* __restrict__ bsh) {
    int row = blockIdx.x;
    int tid = threadIdx.x, lane = tid & 31, warp = tid >> 5;
    const float4* xr = (const float4*)(X + (size_t)row * DIM);
    float4 v = xr[tid];
    float s  = v.x + v.y + v.z + v.w;
    float s2 = v.x * v.x + v.y * v.y + v.z * v.z + v.w * v.w;
    __shared__ float rs[8], rs2[8];
#pragma unroll
    for (int o = 16; o; o >>= 1) {
        s  += __shfl_xor_sync(0xffffffffu, s, o);
        s2 += __shfl_xor_sync(0xffffffffu, s2, o);
    }
    if (lane == 0) { rs[warp] = s; rs2[warp] = s2; }
    __syncthreads();
    float ts = 0.f, ts2 = 0.f;
#pragma unroll
    for (int k = 0; k < 8; k++) { ts += rs[k]; ts2 += rs2[k]; }
    float mean = ts * (1.f / DIM);
    float var  = ts2 * (1.f / DIM) - mean * mean;
    float inv  = rsqrtf(var + 1e-5f);
    float4 gv = ((const float4*)g)[tid];
    float4 bv = ((const float4*)bsh)[tid];
    float4 o;
    o.x = (v.x - mean) * inv * gv.x + bv.x;
    o.y = (v.y - mean) * inv * gv.y + bv.y;
    o.z = (v.z - mean) * inv * gv.z + bv.z;
    o.w = (v.w - mean) * inv * gv.w + bv.w;
    ((float4*)(g_tgt + (size_t)row * DIM))[tid] = o;
    __nv_bfloat162 h0 = __floats2bfloat162_rn(o.x, o.y);
    __nv_bfloat162 h1 = __floats2bfloat162_rn(o.z, o.w);
    uint2 hp = make_uint2(*(unsigned*)&h0, *(unsigned*)&h1);
    ((uint2*)(g_tgtH + (size_t)row * DIM))[tid] = hp;
}

// --------------------------- output head + loss -----------------------------
__global__ void head_kernel(const float* __restrict__ Wh, const float* __restrict__ bh) {
    int n = blockIdx.x, b = blockIdx.y;
    int tid = threadIdx.x;
    const float* xr = g_tgt + (size_t)(b * SEQ + SEQ - 1) * DIM;
    const float* wr = Wh + (size_t)n * DIM;
    float s = 0.f;
    for (int d = tid; d < DIM; d += 128) s += xr[d] * wr[d];
#pragma unroll
    for (int o = 16; o; o >>= 1) s += __shfl_xor_sync(0xffffffffu, s, o);
    __shared__ float red[4];
    if ((tid & 31) == 0) red[tid >> 5] = s;
    __syncthreads();
    if (tid == 0)
        g_hat[b * HAM + n] = red[0] + red[1] + red[2] + red[3] + bh[n];
}

__global__ void loss_kernel(const float* __restrict__ y, const float* __restrict__ w,
                            float* __restrict__ out) {
    int tid = threadIdx.x, lane = tid & 31, warp = tid >> 5;
    float s = 0.f;
    for (int idx = tid; idx < BB * HAM; idx += 256) {
        int b = idx / HAM, j = idx - b * HAM;
        float resid = y[idx] - w[(size_t)(b * 16 + 15) * HAM + j];
        float d = g_hat[idx] - resid;
        s += d * d;
    }
#pragma unroll
    for (int o = 16; o; o >>= 1) s += __shfl_xor_sync(0xffffffffu, s, o);
    __shared__ float red[8];
    if (lane == 0) red[warp] = s;
    __syncthreads();
    if (tid == 0) {
        float t = 0.f;
#pragma unroll
        for (int k = 0; k < 8; k++) t += red[k];
        out[0] = t * (1.f / (BB * HAM));
    }
}

// ------------------------------- launch -------------------------------------
extern "C" void kernel_launch(void* const* d_in, const int* in_sizes, int n_in,
                              void* d_out, int out_size) {
    const float* x      = (const float*)d_in[0];
    const float* w      = (const float*)d_in[1];
    const float* y      = (const float*)d_in[2];
    const float* W_nail = (const float*)d_in[3];
    const float* b_nail = (const float*)d_in[4];
    const float* W_cond = (const float*)d_in[5];
    const float* b_cond = (const float*)d_in[6];
    const float* Wqkv   = (const float*)d_in[7];
    const float* bqkv   = (const float*)d_in[8];
    const float* Wo     = (const float*)d_in[9];
    const float* bo     = (const float*)d_in[10];
    const float* ln1g   = (const float*)d_in[11];
    const float* ln1b   = (const float*)d_in[12];
    const float* ln2g   = (const float*)d_in[13];
    const float* ln2b   = (const float*)d_in[14];
    const float* W1     = (const float*)d_in[15];
    const float* b1     = (const float*)d_in[16];
    const float* W2     = (const float*)d_in[17];
    const float* b2     = (const float*)d_in[18];
    const float* W_ham  = (const float*)d_in[19];
    const float* b_ham  = (const float*)d_in[20];

    void* p;
    bf16 *WqkvH, *WoH, *W1H, *W2H, *tgtH, *qkv, *obuf, *hbuf;
    float *tgt, *x1;
    int* xmask;
    cudaGetSymbolAddress(&p, g_WqkvH); WqkvH = (bf16*)p;
    cudaGetSymbolAddress(&p, g_WoH);   WoH   = (bf16*)p;
    cudaGetSymbolAddress(&p, g_W1H);   W1H   = (bf16*)p;
    cudaGetSymbolAddress(&p, g_W2H);   W2H   = (bf16*)p;
    cudaGetSymbolAddress(&p, g_tgtH);  tgtH  = (bf16*)p;
    cudaGetSymbolAddress(&p, g_qkv);   qkv   = (bf16*)p;
    cudaGetSymbolAddress(&p, g_obuf);  obuf  = (bf16*)p;
    cudaGetSymbolAddress(&p, g_hbuf);  hbuf  = (bf16*)p;
    cudaGetSymbolAddress(&p, g_tgt);   tgt   = (float*)p;
    cudaGetSymbolAddress(&p, g_x1);    x1    = (float*)p;
    cudaGetSymbolAddress(&p, g_xmask); xmask = (int*)p;

    cudaFuncSetAttribute(gemm_tc<2>, cudaFuncAttributeMaxDynamicSharedMemorySize, G_SMEM);
    cudaFuncSetAttribute(gemm_tc<3>, cudaFuncAttributeMaxDynamicSharedMemorySize, G_SMEM);
    cudaFuncSetAttribute(gemm_tc<4>, cudaFuncAttributeMaxDynamicSharedMemorySize, G_SMEM);
    cudaFuncSetAttribute(flash_kernel, cudaFuncAttributeMaxDynamicSharedMemorySize, FA_SMEM);

    // weight conversion fp32 -> bf16 (every launch: deterministic)
    {
        int n;
        n = NLAY * QKVD * DIM / 4; f2h4_kernel<<<(n + 255) / 256, 256>>>((const float4*)Wqkv, (__nv_bfloat162*)WqkvH, n);
        n = NLAY * DIM * DIM / 4;  f2h4_kernel<<<(n + 255) / 256, 256>>>((const float4*)Wo,   (__nv_bfloat162*)WoH,   n);
        n = NLAY * FFD * DIM / 4;  f2h4_kernel<<<(n + 255) / 256, 256>>>((const float4*)W1,   (__nv_bfloat162*)W1H,   n);
        n = NLAY * DIM * FFD / 4;  f2h4_kernel<<<(n + 255) / 256, 256>>>((const float4*)W2,   (__nv_bfloat162*)W2H,   n);
    }

    embed_x_kernel<<<512, 256>>>(x, W_nail, b_nail);
    embed_w_kernel<<<384, 256>>>(w, W_cond, b_cond);

    for (int l = 0; l < NLAY; l++) {
        // QKV projection: (7168x1024)@(3072x1024)^T + bias -> bf16
        gemm_tc<2><<<dim3(QKVD / 128, MTOK / 128), 128, G_SMEM>>>(
            tgtH, WqkvH + (size_t)l * QKVD * DIM, nullptr, qkv,
            bqkv + l * QKVD, nullptr, MTOK, QKVD, DIM);

        // fused attention -> obuf (b, s, h*64+d) bf16
        flash_kernel<<<dim3(SEQ / 128, BB * NH), 256, FA_SMEM>>>(qkv, obuf, xmask);

        // O projection + bias + residual -> fp32 X1
        gemm_tc<3><<<dim3(DIM / 128, MTOK / 128), 128, G_SMEM>>>(
            obuf, WoH + (size_t)l * DIM * DIM, x1, nullptr,
            bo + l * DIM, tgt, MTOK, DIM, DIM);

        ln_kernel<<<MTOK, 256>>>(x1, ln1g + l * DIM, ln1b + l * DIM);

        // FF1 + bias + exact GELU -> bf16
        gemm_tc<4><<<dim3(FFD / 128, MTOK / 128), 128, G_SMEM>>>(
            tgtH, W1H + (size_t)l * FFD * DIM, nullptr, hbuf,
            b1 + l * FFD, nullptr, MTOK, FFD, DIM);

        // FF2 + bias + residual -> fp32 X1
        gemm_tc<3><<<dim3(DIM / 128, MTOK / 128), 128, G_SMEM>>>(
            hbuf, W2H + (size_t)l * DIM * FFD, x1, nullptr,
            b2 + l * DIM, tgt, MTOK, DIM, FFD);

        ln_kernel<<<MTOK, 256>>>(x1, ln2g + l * DIM, ln2b + l * DIM);
    }

    head_kernel<<<dim3(HAM, BB), 128>>>(W_ham, b_ham);
    loss_kernel<<<1, 256>>>(y, w, (float*)d_out);
}